// round 8
// baseline (speedup 1.0000x reference)
#include <cuda_runtime.h>
#include <cuda_bf16.h>
#include <math.h>
#include <stdint.h>

#define T_SEQ 512
#define BATCH 64
#define HDIM  512
#define EDIM  300
#define G3    1536   // 3*H
#define NCOLS 4608   // 3 * G3
#define NB    144    // 72 n-tiles(64) x 2 k-halves(256), 1 CTA/SM
#define NGRP  12     // barrier groups
#define GSZ   12     // CTAs per group

#define KXP   320    // xp0 K padded (300 -> 320)

// ---------------- device scratch (no allocations) ----------------
__device__ float g_xp0[T_SEQ * BATCH * G3];        // layer-0 input projections
__device__ float g_gh [2 * BATCH * NCOLS];         // split-K partial GEMM outputs
__device__ float g_h2h[T_SEQ * BATCH * HDIM];      // layer-1 fp32 history (for final)
__device__ __nv_bfloat16 g_h1hi[T_SEQ * BATCH * HDIM];
__device__ __nv_bfloat16 g_h1lo[T_SEQ * BATCH * HDIM];
__device__ __nv_bfloat16 g_h2hi[T_SEQ * BATCH * HDIM];
__device__ __nv_bfloat16 g_h2lo[T_SEQ * BATCH * HDIM];
__device__ __nv_bfloat16 g_ehi[30000 * KXP];       // emb bf16 hi (K padded w/ zeros)
__device__ __nv_bfloat16 g_elo[30000 * KXP];
__device__ __nv_bfloat16 g_w0hi[G3 * KXP];         // Wih0 bf16 hi
__device__ __nv_bfloat16 g_w0lo[G3 * KXP];
// hierarchical barrier state: monotonic counters (mod-checked, never reset)
__device__ unsigned g_cnt1[NGRP * 32];             // group counters, 128B apart
__device__ unsigned g_cnt2;                        // root counter
__device__ volatile unsigned g_gen;                // generation

// fast transcendentals (MUFU-based; rel err ~1e-6, overflow-safe)
__device__ __forceinline__ float fsig_(float x) { return 1.0f / (1.0f + __expf(-x)); }
__device__ __forceinline__ float ftanh_(float x) {
    float t = __expf(-2.0f * fabsf(x));          // t in (0,1]
    return copysignf(__fdividef(1.0f - t, 1.0f + t), x);
}

// ---------------- warp MMA helpers (sm_80+ PTX: valid on base sm_103) ----------------
__device__ __forceinline__ uint32_t smem_u32_(const void* p) {
    uint32_t a;
    asm("{ .reg .u64 t; cvta.to.shared.u64 t, %1; cvt.u32.u64 %0, t; }" : "=r"(a) : "l"(p));
    return a;
}
__device__ __forceinline__ void ldsm4_(uint32_t& a0, uint32_t& a1, uint32_t& a2,
                                       uint32_t& a3, uint32_t addr) {
    asm volatile("ldmatrix.sync.aligned.m8n8.x4.shared.b16 {%0,%1,%2,%3}, [%4];"
                 : "=r"(a0), "=r"(a1), "=r"(a2), "=r"(a3) : "r"(addr));
}
__device__ __forceinline__ void mma16816_(float* c, uint32_t a0, uint32_t a1,
                                          uint32_t a2, uint32_t a3,
                                          uint32_t b0, uint32_t b1) {
    asm volatile("mma.sync.aligned.m16n8k16.row.col.f32.bf16.bf16.f32 "
                 "{%0,%1,%2,%3}, {%4,%5,%6,%7}, {%8,%9}, {%0,%1,%2,%3};"
                 : "+f"(c[0]), "+f"(c[1]), "+f"(c[2]), "+f"(c[3])
                 : "r"(a0), "r"(a1), "r"(a2), "r"(a3), "r"(b0), "r"(b1));
}

// pack fp32x4 -> bf16 hi and lo uint2
__device__ __forceinline__ void split_hl_(float4 v, uint2& hi, uint2& lo) {
    __nv_bfloat16 h0 = __float2bfloat16(v.x), h1 = __float2bfloat16(v.y);
    __nv_bfloat16 h2 = __float2bfloat16(v.z), h3 = __float2bfloat16(v.w);
    __nv_bfloat16 l0 = __float2bfloat16(v.x - __bfloat162float(h0));
    __nv_bfloat16 l1 = __float2bfloat16(v.y - __bfloat162float(h1));
    __nv_bfloat16 l2 = __float2bfloat16(v.z - __bfloat162float(h2));
    __nv_bfloat16 l3 = __float2bfloat16(v.w - __bfloat162float(h3));
    hi = make_uint2(((uint32_t)__bfloat16_as_ushort(h1) << 16) | __bfloat16_as_ushort(h0),
                    ((uint32_t)__bfloat16_as_ushort(h3) << 16) | __bfloat16_as_ushort(h2));
    lo = make_uint2(((uint32_t)__bfloat16_as_ushort(l1) << 16) | __bfloat16_as_ushort(l0),
                    ((uint32_t)__bfloat16_as_ushort(l3) << 16) | __bfloat16_as_ushort(l2));
}

// ---------------- hierarchical grid barrier (12 groups x 12) ----------------
__device__ __forceinline__ void grid_sync(int grp) {
    __syncthreads();
    if (threadIdx.x == 0) {
        const unsigned old = g_gen;
        __threadfence();                                   // release my writes
        if ((atomicAdd(&g_cnt1[grp * 32], 1u) + 1u) % GSZ == 0u) {
            if ((atomicAdd(&g_cnt2, 1u) + 1u) % NGRP == 0u) {
                __threadfence();
                g_gen = old + 1u;                          // release
            }
        }
        while (g_gen == old) { }
        __threadfence();                                   // acquire
    }
    __syncthreads();
}

// =====================================================================
// prep: fp32 -> bf16 hi/lo for emb (30000x300, pad K to 320) and Wih0 (1536x300)
// =====================================================================
#define PREP_E (30000 * (KXP / 4))
#define PREP_W (G3 * (KXP / 4))
__global__ __launch_bounds__(256) void prep_kernel(const float* __restrict__ emb,
                                                   const float* __restrict__ Wih0) {
    const int id = blockIdx.x * 256 + threadIdx.x;
    if (id < PREP_E) {
        const int row = id / (KXP / 4), q = id % (KXP / 4);
        float4 v = (4 * q + 3 < EDIM)
                       ? *reinterpret_cast<const float4*>(emb + row * EDIM + 4 * q)
                       : make_float4(0.f, 0.f, 0.f, 0.f);
        uint2 hi, lo;
        split_hl_(v, hi, lo);
        *reinterpret_cast<uint2*>(&g_ehi[row * KXP + 4 * q]) = hi;
        *reinterpret_cast<uint2*>(&g_elo[row * KXP + 4 * q]) = lo;
    } else if (id < PREP_E + PREP_W) {
        const int wd = id - PREP_E;
        const int row = wd / (KXP / 4), q = wd % (KXP / 4);
        float4 v = (4 * q + 3 < EDIM)
                       ? *reinterpret_cast<const float4*>(Wih0 + row * EDIM + 4 * q)
                       : make_float4(0.f, 0.f, 0.f, 0.f);
        uint2 hi, lo;
        split_hl_(v, hi, lo);
        *reinterpret_cast<uint2*>(&g_w0hi[row * KXP + 4 * q]) = hi;
        *reinterpret_cast<uint2*>(&g_w0lo[row * KXP + 4 * q]) = lo;
    }
}

// =====================================================================
// xp0 via HMMA bf16 hi/lo: xp0 = emb[texts] @ Wih0^T + bih0  (known-good)
// =====================================================================
#define XSTR  656
#define XSM_AH 0
#define XSM_AL (64 * XSTR)
#define XSM_BH (2 * 64 * XSTR)
#define XSM_BL (3 * 64 * XSTR)
#define SMEM_XP0 (4 * 64 * XSTR)   // 167936

__global__ __launch_bounds__(256) void xp0_mma_kernel(const int* __restrict__ texts,
                                                      const float* __restrict__ bih0) {
    extern __shared__ char sm[];
    const uint32_t sb = smem_u32_(sm);
    const int tid = threadIdx.x;
    const int wid = tid >> 5;
    const int lane = tid & 31;
    const int n0 = blockIdx.x * 64;
    const int m0 = blockIdx.y * 64;

    for (int idx = tid; idx < 2560; idx += 256) {     // 64 rows * 40 uint4
        const int row = idx / 40, q = idx % 40;
        const int tok = texts[m0 + row];
        *reinterpret_cast<uint4*>(sm + XSM_AH + row * XSTR + 16 * q) =
            reinterpret_cast<const uint4*>(g_ehi + tok * KXP)[q];
        *reinterpret_cast<uint4*>(sm + XSM_AL + row * XSTR + 16 * q) =
            reinterpret_cast<const uint4*>(g_elo + tok * KXP)[q];
        *reinterpret_cast<uint4*>(sm + XSM_BH + row * XSTR + 16 * q) =
            reinterpret_cast<const uint4*>(g_w0hi + (n0 + row) * KXP)[q];
        *reinterpret_cast<uint4*>(sm + XSM_BL + row * XSTR + 16 * q) =
            reinterpret_cast<const uint4*>(g_w0lo + (n0 + row) * KXP)[q];
    }
    __syncthreads();

    const int mg = (wid & 3) * 16;
    const int ng = (wid >> 2) * 32;
    const uint32_t aoff = sb + (uint32_t)((mg + (lane & 15)) * XSTR + (lane >> 4) * 16);
    const uint32_t boff = sb + (uint32_t)((ng + (lane & 7) + ((lane >> 4) << 3)) * XSTR +
                                          ((lane >> 3) & 1) * 16);

    float acc[4][4];
#pragma unroll
    for (int t = 0; t < 4; t++)
#pragma unroll
        for (int j = 0; j < 4; j++) acc[t][j] = 0.0f;

#pragma unroll 4
    for (int ks = 0; ks < KXP / 16; ++ks) {
        uint32_t ah0, ah1, ah2, ah3, al0, al1, al2, al3;
        ldsm4_(ah0, ah1, ah2, ah3, aoff + XSM_AH + ks * 32);
        ldsm4_(al0, al1, al2, al3, aoff + XSM_AL + ks * 32);
        uint32_t bh0, bh1, bh2, bh3, bg0, bg1, bg2, bg3;
        ldsm4_(bh0, bh1, bh2, bh3, boff + XSM_BH + ks * 32);
        ldsm4_(bg0, bg1, bg2, bg3, boff + XSM_BH + 16 * XSTR + ks * 32);
        uint32_t bl0, bl1, bl2, bl3, bm0, bm1, bm2, bm3;
        ldsm4_(bl0, bl1, bl2, bl3, boff + XSM_BL + ks * 32);
        ldsm4_(bm0, bm1, bm2, bm3, boff + XSM_BL + 16 * XSTR + ks * 32);
        mma16816_(acc[0], ah0, ah1, ah2, ah3, bh0, bh1);
        mma16816_(acc[1], ah0, ah1, ah2, ah3, bh2, bh3);
        mma16816_(acc[2], ah0, ah1, ah2, ah3, bg0, bg1);
        mma16816_(acc[3], ah0, ah1, ah2, ah3, bg2, bg3);
        mma16816_(acc[0], al0, al1, al2, al3, bh0, bh1);
        mma16816_(acc[1], al0, al1, al2, al3, bh2, bh3);
        mma16816_(acc[2], al0, al1, al2, al3, bg0, bg1);
        mma16816_(acc[3], al0, al1, al2, al3, bg2, bg3);
        mma16816_(acc[0], ah0, ah1, ah2, ah3, bl0, bl1);
        mma16816_(acc[1], ah0, ah1, ah2, ah3, bl2, bl3);
        mma16816_(acc[2], ah0, ah1, ah2, ah3, bm0, bm1);
        mma16816_(acc[3], ah0, ah1, ah2, ah3, bm2, bm3);
    }

    const int crow = lane >> 2;
    const int ccol = (lane & 3) * 2;
#pragma unroll
    for (int nt = 0; nt < 4; ++nt) {
        const int n = n0 + ng + nt * 8 + ccol;
        const float b0 = bih0[n], b1 = bih0[n + 1];
        const int m = m0 + mg + crow;
        *reinterpret_cast<float2*>(&g_xp0[m * G3 + n]) =
            make_float2(acc[nt][0] + b0, acc[nt][1] + b1);
        *reinterpret_cast<float2*>(&g_xp0[(m + 8) * G3 + n]) =
            make_float2(acc[nt][2] + b0, acc[nt][3] + b1);
    }
}

// =====================================================================
// Persistent recurrence. 144 CTAs = 72 n-tiles(64) x 2 K-halves(256).
// Warp tile 16m x 32n (4 acc chains). A fill = bf16 hi/lo copy.
// Gate fused, spread over ALL 144 CTAs (114 quads each), hprev in regs.
// =====================================================================
#define RSTR  528
#define RSM_AH 0
#define RSM_AL (64 * RSTR)
#define RSM_BH (2 * 64 * RSTR)
#define RSM_BL (3 * 64 * RSTR)
#define SMEM_REC (4 * 64 * RSTR)   // 135168

#define LD4_(d, p)  { float4 _t = *reinterpret_cast<const float4*>(p); d[0]=_t.x; d[1]=_t.y; d[2]=_t.z; d[3]=_t.w; }
#define ADD4_(d, p) { float4 _t = *reinterpret_cast<const float4*>(p); d[0]+=_t.x; d[1]+=_t.y; d[2]+=_t.z; d[3]+=_t.w; }

__global__ __launch_bounds__(256) void recurrence_kernel(const float* __restrict__ Whh0,
                                                         const float* __restrict__ Wih1,
                                                         const float* __restrict__ Whh1,
                                                         const float* bhh0,
                                                         const float* bih1,
                                                         const float* bhh1) {
    extern __shared__ char sm[];
    const uint32_t sb = smem_u32_(sm);
    const int tid = threadIdx.x;
    const int wid = tid >> 5;
    const int lane = tid & 31;
    const int cta = blockIdx.x;
    const int grp = cta / GSZ;
    const int nt0 = cta % 72;
    const int kt  = cta / 72;
    const int n0  = nt0 * 64;
    const int k0  = kt * 256;

    const float* W;
    int wr0, cls;
    if (n0 < G3)          { W = Whh0; wr0 = n0;          cls = 0; }
    else if (n0 < 2 * G3) { W = Wih1; wr0 = n0 - G3;     cls = 1; }
    else                  { W = Whh1; wr0 = n0 - 2 * G3; cls = 2; }

    // ---- prologue: weight tile (64 n-rows x 256 k) -> bf16 hi/lo in SMEM ----
    for (int idx = tid; idx < 4096; idx += 256) {   // 64 rows * 64 float4
        const int row = idx >> 6, q = idx & 63;
        float4 v = *reinterpret_cast<const float4*>(W + (wr0 + row) * HDIM + k0 + 4 * q);
        uint2 hi, lo;
        split_hl_(v, hi, lo);
        *reinterpret_cast<uint2*>(sm + RSM_BH + row * RSTR + 8 * q) = hi;
        *reinterpret_cast<uint2*>(sm + RSM_BL + row * RSTR + 8 * q) = lo;
    }

    // ---- static gate assignment: 114 quads per CTA across all 144 CTAs ----
    const int qid = cta * 114 + tid;
    const bool gvalid = (tid < 114) && (qid < 2 * BATCH * HDIM / 4);
    const int glayer = qid >> 13;
    const int gb = (qid >> 7) & 63;
    const int gh4 = (qid & 127) * 4;
    float hp[4] = {0.f, 0.f, 0.f, 0.f};   // persistent h_prev

    // warp geometry: 16m x 32n (4 acc chains)
    const int mg = (wid & 3) * 16;
    const int ng = (wid >> 2) * 32;
    const uint32_t aoff = sb + (uint32_t)((mg + (lane & 15)) * RSTR + (lane >> 4) * 16);
    const uint32_t boff = sb + (uint32_t)((ng + (lane & 7) + ((lane >> 4) << 3)) * RSTR +
                                          ((lane >> 3) & 1) * 16);

    __syncthreads();

    for (int iter = 0; iter <= T_SEQ; ++iter) {
        const bool active = (iter > 0) && !(cls == 0 && iter > 511) && !(cls == 2 && iter < 2);
        if (active) {
            const int tsrc = (cls == 2) ? iter - 2 : iter - 1;
            const __nv_bfloat16* shi = ((cls == 2) ? g_h2hi : g_h1hi) + tsrc * BATCH * HDIM;
            const __nv_bfloat16* slo = ((cls == 2) ? g_h2lo : g_h1lo) + tsrc * BATCH * HDIM;
            // fill A: bf16 copy of the K-half, 64 rows x 256 k (32 uint4/row)
            for (int idx = tid; idx < 2048; idx += 256) {
                const int row = idx >> 5, q = idx & 31;
                *reinterpret_cast<uint4*>(sm + RSM_AH + row * RSTR + 16 * q) =
                    reinterpret_cast<const uint4*>(shi + row * HDIM + k0)[q];
                *reinterpret_cast<uint4*>(sm + RSM_AL + row * RSTR + 16 * q) =
                    reinterpret_cast<const uint4*>(slo + row * HDIM + k0)[q];
            }
            __syncthreads();

            float acc[4][4];
#pragma unroll
            for (int t = 0; t < 4; t++)
#pragma unroll
                for (int j = 0; j < 4; j++) acc[t][j] = 0.0f;

#pragma unroll 8
            for (int ks = 0; ks < 16; ++ks) {
                uint32_t ah0, ah1, ah2, ah3, al0, al1, al2, al3;
                ldsm4_(ah0, ah1, ah2, ah3, aoff + RSM_AH + ks * 32);
                ldsm4_(al0, al1, al2, al3, aoff + RSM_AL + ks * 32);
                uint32_t bh0, bh1, bh2, bh3, bg0, bg1, bg2, bg3;
                ldsm4_(bh0, bh1, bh2, bh3, boff + RSM_BH + ks * 32);
                ldsm4_(bg0, bg1, bg2, bg3, boff + RSM_BH + 16 * RSTR + ks * 32);
                uint32_t bl0, bl1, bl2, bl3, bm0, bm1, bm2, bm3;
                ldsm4_(bl0, bl1, bl2, bl3, boff + RSM_BL + ks * 32);
                ldsm4_(bm0, bm1, bm2, bm3, boff + RSM_BL + 16 * RSTR + ks * 32);
                mma16816_(acc[0], ah0, ah1, ah2, ah3, bh0, bh1);
                mma16816_(acc[1], ah0, ah1, ah2, ah3, bh2, bh3);
                mma16816_(acc[2], ah0, ah1, ah2, ah3, bg0, bg1);
                mma16816_(acc[3], ah0, ah1, ah2, ah3, bg2, bg3);
                mma16816_(acc[0], al0, al1, al2, al3, bh0, bh1);
                mma16816_(acc[1], al0, al1, al2, al3, bh2, bh3);
                mma16816_(acc[2], al0, al1, al2, al3, bg0, bg1);
                mma16816_(acc[3], al0, al1, al2, al3, bg2, bg3);
                mma16816_(acc[0], ah0, ah1, ah2, ah3, bl0, bl1);
                mma16816_(acc[1], ah0, ah1, ah2, ah3, bl2, bl3);
                mma16816_(acc[2], ah0, ah1, ah2, ah3, bm0, bm1);
                mma16816_(acc[3], ah0, ah1, ah2, ah3, bm2, bm3);
            }

            // epilogue: write partials to this K-half's gh buffer
            const int crow = lane >> 2;
            const int ccol = (lane & 3) * 2;
            float* outp = g_gh + kt * BATCH * NCOLS;
#pragma unroll
            for (int nt = 0; nt < 4; ++nt) {
                const int n = n0 + ng + nt * 8 + ccol;
                const int b = mg + crow;
                *reinterpret_cast<float2*>(outp + b * NCOLS + n) =
                    make_float2(acc[nt][0], acc[nt][1]);
                *reinterpret_cast<float2*>(outp + (b + 8) * NCOLS + n) =
                    make_float2(acc[nt][2], acc[nt][3]);
            }
        }
        grid_sync(grp);          // gh partials visible to gate owners

        // ---- fused gate (register-resident hprev; sums both K-halves) ----
        if (gvalid) {
            const float* gha = g_gh + gb * NCOLS;
            const float* ghb = g_gh + BATCH * NCOLS + gb * NCOLS;
            if (glayer == 0) {
                if (iter < T_SEQ) {
                    const float* xp = &g_xp0[(iter * BATCH + gb) * G3];
                    float xr[4], xz[4], xn[4], hr[4], hz[4], hn[4];
                    LD4_(xr, xp + gh4); LD4_(xz, xp + HDIM + gh4); LD4_(xn, xp + 2 * HDIM + gh4);
                    LD4_(hr, bhh0 + gh4); LD4_(hz, bhh0 + HDIM + gh4); LD4_(hn, bhh0 + 2 * HDIM + gh4);
                    if (iter > 0) {
                        ADD4_(hr, gha + gh4);            ADD4_(hr, ghb + gh4);
                        ADD4_(hz, gha + HDIM + gh4);     ADD4_(hz, ghb + HDIM + gh4);
                        ADD4_(hn, gha + 2 * HDIM + gh4); ADD4_(hn, ghb + 2 * HDIM + gh4);
                    }
#pragma unroll
                    for (int j = 0; j < 4; j++) {
                        float r = fsig_(xr[j] + hr[j]);
                        float z = fsig_(xz[j] + hz[j]);
                        float n = ftanh_(xn[j] + r * hn[j]);
                        hp[j] = (1.0f - z) * n + z * hp[j];
                    }
                    uint2 hi, lo;
                    split_hl_(make_float4(hp[0], hp[1], hp[2], hp[3]), hi, lo);
                    const int off = (iter * BATCH + gb) * HDIM + gh4;
                    *reinterpret_cast<uint2*>(&g_h1hi[off]) = hi;
                    *reinterpret_cast<uint2*>(&g_h1lo[off]) = lo;
                }
            } else {
                if (iter >= 1) {
                    const int t = iter - 1;
                    float xr[4], xz[4], xn[4], hr[4], hz[4], hn[4];
                    LD4_(xr, bih1 + gh4); LD4_(xz, bih1 + HDIM + gh4); LD4_(xn, bih1 + 2 * HDIM + gh4);
                    ADD4_(xr, gha + G3 + gh4);            ADD4_(xr, ghb + G3 + gh4);
                    ADD4_(xz, gha + G3 + HDIM + gh4);     ADD4_(xz, ghb + G3 + HDIM + gh4);
                    ADD4_(xn, gha + G3 + 2 * HDIM + gh4); ADD4_(xn, ghb + G3 + 2 * HDIM + gh4);
                    LD4_(hr, bhh1 + gh4); LD4_(hz, bhh1 + HDIM + gh4); LD4_(hn, bhh1 + 2 * HDIM + gh4);
                    if (t > 0) {
                        ADD4_(hr, gha + 2 * G3 + gh4);            ADD4_(hr, ghb + 2 * G3 + gh4);
                        ADD4_(hz, gha + 2 * G3 + HDIM + gh4);     ADD4_(hz, ghb + 2 * G3 + HDIM + gh4);
                        ADD4_(hn, gha + 2 * G3 + 2 * HDIM + gh4); ADD4_(hn, ghb + 2 * G3 + 2 * HDIM + gh4);
                    }
#pragma unroll
                    for (int j = 0; j < 4; j++) {
                        float r = fsig_(xr[j] + hr[j]);
                        float z = fsig_(xz[j] + hz[j]);
                        float n = ftanh_(xn[j] + r * hn[j]);
                        hp[j] = (1.0f - z) * n + z * hp[j];
                    }
                    const int off = (t * BATCH + gb) * HDIM + gh4;
                    *reinterpret_cast<float4*>(&g_h2h[off]) =
                        make_float4(hp[0], hp[1], hp[2], hp[3]);
                    uint2 hi, lo;
                    split_hl_(make_float4(hp[0], hp[1], hp[2], hp[3]), hi, lo);
                    *reinterpret_cast<uint2*>(&g_h2hi[off]) = hi;
                    *reinterpret_cast<uint2*>(&g_h2lo[off]) = lo;
                }
            }
        }
        grid_sync(grp);          // h hi/lo visible to next GEMM
    }
}

// =====================================================================
// pooled[t][h] = mean_b h2[t][b][h];  out[t][l] = pooled . fc_W[l] + fc_b[l]
// =====================================================================
__global__ __launch_bounds__(512) void final_kernel(const float* __restrict__ fc_W,
                                                    const float* __restrict__ fc_b,
                                                    float* __restrict__ out) {
    __shared__ float pooled[HDIM];
    const int t = blockIdx.x;
    const int h = threadIdx.x;

    float s = 0.0f;
    const float* base = &g_h2h[t * BATCH * HDIM + h];
#pragma unroll 8
    for (int b = 0; b < BATCH; ++b) s += base[b * HDIM];
    pooled[h] = s * (1.0f / (float)BATCH);
    __syncthreads();

    const int w = h >> 5, lane = h & 31;
    if (w < 5) {
        float acc = 0.0f;
        for (int k = lane; k < HDIM; k += 32) acc += pooled[k] * fc_W[w * HDIM + k];
#pragma unroll
        for (int o = 16; o > 0; o >>= 1) acc += __shfl_xor_sync(0xFFFFFFFFu, acc, o);
        if (lane == 0) out[t * 5 + w] = acc + fc_b[w];
    }
}

// =====================================================================
extern "C" void kernel_launch(void* const* d_in, const int* in_sizes, int n_in,
                              void* d_out, int out_size) {
    const int*   texts = (const int*)  d_in[0];
    const float* emb   = (const float*)d_in[1];
    const float* Wih0  = (const float*)d_in[2];
    const float* Whh0  = (const float*)d_in[3];
    const float* bih0  = (const float*)d_in[4];
    const float* bhh0  = (const float*)d_in[5];
    const float* Wih1  = (const float*)d_in[6];
    const float* Whh1  = (const float*)d_in[7];
    const float* bih1  = (const float*)d_in[8];
    const float* bhh1  = (const float*)d_in[9];
    const float* fc_W  = (const float*)d_in[10];
    const float* fc_b  = (const float*)d_in[11];
    float* out = (float*)d_out;

    cudaFuncSetAttribute(xp0_mma_kernel,
                         cudaFuncAttributeMaxDynamicSharedMemorySize, SMEM_XP0);
    cudaFuncSetAttribute(recurrence_kernel,
                         cudaFuncAttributeMaxDynamicSharedMemorySize, SMEM_REC);

    prep_kernel<<<(PREP_E + PREP_W + 255) / 256, 256>>>(emb, Wih0);
    xp0_mma_kernel<<<dim3(24, 512), 256, SMEM_XP0>>>(texts, bih0);
    recurrence_kernel<<<NB, 256, SMEM_REC>>>(Whh0, Wih1, Whh1, bhh0, bih1, bhh1);
    final_kernel<<<T_SEQ, 512>>>(fc_W, fc_b, out);
}

// round 9
// speedup vs baseline: 1.4602x; 1.4602x over previous
#include <cuda_runtime.h>
#include <cuda_bf16.h>
#include <math.h>
#include <stdint.h>

#define T_SEQ 512
#define BATCH 64
#define HDIM  512
#define EDIM  300
#define G3    1536   // 3*H
#define NCOLS 4608   // 3 * G3
#define NB    144    // 72 n-tiles(64) x 2 k-halves(256), 1 CTA/SM

#define KXP   320    // xp0 K padded (300 -> 320)

// ---------------- device scratch (no allocations) ----------------
__device__ float g_xp0[T_SEQ * BATCH * G3];        // layer-0 input projections
__device__ float g_gh [2 * BATCH * NCOLS];         // split-K partial GEMM outputs
__device__ float g_h2h[T_SEQ * BATCH * HDIM];      // layer-1 fp32 history (for final)
__device__ __nv_bfloat16 g_h1hi[T_SEQ * BATCH * HDIM];
__device__ __nv_bfloat16 g_h1lo[T_SEQ * BATCH * HDIM];
__device__ __nv_bfloat16 g_h2hi[T_SEQ * BATCH * HDIM];
__device__ __nv_bfloat16 g_h2lo[T_SEQ * BATCH * HDIM];
__device__ __nv_bfloat16 g_ehi[30000 * KXP];       // emb bf16 hi (K padded w/ zeros)
__device__ __nv_bfloat16 g_elo[30000 * KXP];
__device__ __nv_bfloat16 g_w0hi[G3 * KXP];         // Wih0 bf16 hi
__device__ __nv_bfloat16 g_w0lo[G3 * KXP];
__device__ unsigned g_cnt;
__device__ volatile unsigned g_gen;

// fast transcendentals (MUFU-based; rel err ~1e-6, overflow-safe)
__device__ __forceinline__ float fsig_(float x) { return 1.0f / (1.0f + __expf(-x)); }
__device__ __forceinline__ float ftanh_(float x) {
    float t = __expf(-2.0f * fabsf(x));          // t in (0,1]
    return copysignf(__fdividef(1.0f - t, 1.0f + t), x);
}

// ---------------- warp MMA helpers (sm_80+ PTX: valid on base sm_103) ----------------
__device__ __forceinline__ uint32_t smem_u32_(const void* p) {
    uint32_t a;
    asm("{ .reg .u64 t; cvta.to.shared.u64 t, %1; cvt.u32.u64 %0, t; }" : "=r"(a) : "l"(p));
    return a;
}
__device__ __forceinline__ void ldsm4_(uint32_t& a0, uint32_t& a1, uint32_t& a2,
                                       uint32_t& a3, uint32_t addr) {
    asm volatile("ldmatrix.sync.aligned.m8n8.x4.shared.b16 {%0,%1,%2,%3}, [%4];"
                 : "=r"(a0), "=r"(a1), "=r"(a2), "=r"(a3) : "r"(addr));
}
__device__ __forceinline__ void mma16816_(float* c, uint32_t a0, uint32_t a1,
                                          uint32_t a2, uint32_t a3,
                                          uint32_t b0, uint32_t b1) {
    asm volatile("mma.sync.aligned.m16n8k16.row.col.f32.bf16.bf16.f32 "
                 "{%0,%1,%2,%3}, {%4,%5,%6,%7}, {%8,%9}, {%0,%1,%2,%3};"
                 : "+f"(c[0]), "+f"(c[1]), "+f"(c[2]), "+f"(c[3])
                 : "r"(a0), "r"(a1), "r"(a2), "r"(a3), "r"(b0), "r"(b1));
}

// pack fp32x4 -> bf16 hi and lo uint2
__device__ __forceinline__ void split_hl_(float4 v, uint2& hi, uint2& lo) {
    __nv_bfloat16 h0 = __float2bfloat16(v.x), h1 = __float2bfloat16(v.y);
    __nv_bfloat16 h2 = __float2bfloat16(v.z), h3 = __float2bfloat16(v.w);
    __nv_bfloat16 l0 = __float2bfloat16(v.x - __bfloat162float(h0));
    __nv_bfloat16 l1 = __float2bfloat16(v.y - __bfloat162float(h1));
    __nv_bfloat16 l2 = __float2bfloat16(v.z - __bfloat162float(h2));
    __nv_bfloat16 l3 = __float2bfloat16(v.w - __bfloat162float(h3));
    hi = make_uint2(((uint32_t)__bfloat16_as_ushort(h1) << 16) | __bfloat16_as_ushort(h0),
                    ((uint32_t)__bfloat16_as_ushort(h3) << 16) | __bfloat16_as_ushort(h2));
    lo = make_uint2(((uint32_t)__bfloat16_as_ushort(l1) << 16) | __bfloat16_as_ushort(l0),
                    ((uint32_t)__bfloat16_as_ushort(l3) << 16) | __bfloat16_as_ushort(l2));
}

// ---------------- flat grid barrier (R7-proven) + spin backoff ----------------
__device__ __forceinline__ void grid_sync() {
    __syncthreads();
    if (threadIdx.x == 0) {
        unsigned old = g_gen;
        __threadfence();
        if (atomicAdd(&g_cnt, 1u) == NB - 1) {
            g_cnt = 0;
            __threadfence();
            g_gen = old + 1;
        } else {
            while (g_gen == old) { __nanosleep(64); }
        }
        __threadfence();
    }
    __syncthreads();
}

// =====================================================================
// prep: fp32 -> bf16 hi/lo for emb (30000x300, pad K to 320) and Wih0 (1536x300)
// =====================================================================
#define PREP_E (30000 * (KXP / 4))
#define PREP_W (G3 * (KXP / 4))
__global__ __launch_bounds__(256) void prep_kernel(const float* __restrict__ emb,
                                                   const float* __restrict__ Wih0) {
    const int id = blockIdx.x * 256 + threadIdx.x;
    if (id < PREP_E) {
        const int row = id / (KXP / 4), q = id % (KXP / 4);
        float4 v = (4 * q + 3 < EDIM)
                       ? *reinterpret_cast<const float4*>(emb + row * EDIM + 4 * q)
                       : make_float4(0.f, 0.f, 0.f, 0.f);
        uint2 hi, lo;
        split_hl_(v, hi, lo);
        *reinterpret_cast<uint2*>(&g_ehi[row * KXP + 4 * q]) = hi;
        *reinterpret_cast<uint2*>(&g_elo[row * KXP + 4 * q]) = lo;
    } else if (id < PREP_E + PREP_W) {
        const int wd = id - PREP_E;
        const int row = wd / (KXP / 4), q = wd % (KXP / 4);
        float4 v = (4 * q + 3 < EDIM)
                       ? *reinterpret_cast<const float4*>(Wih0 + row * EDIM + 4 * q)
                       : make_float4(0.f, 0.f, 0.f, 0.f);
        uint2 hi, lo;
        split_hl_(v, hi, lo);
        *reinterpret_cast<uint2*>(&g_w0hi[row * KXP + 4 * q]) = hi;
        *reinterpret_cast<uint2*>(&g_w0lo[row * KXP + 4 * q]) = lo;
    }
}

// =====================================================================
// xp0 via HMMA bf16 hi/lo: xp0 = emb[texts] @ Wih0^T + bih0  (known-good)
// =====================================================================
#define XSTR  656
#define XSM_AH 0
#define XSM_AL (64 * XSTR)
#define XSM_BH (2 * 64 * XSTR)
#define XSM_BL (3 * 64 * XSTR)
#define SMEM_XP0 (4 * 64 * XSTR)   // 167936

__global__ __launch_bounds__(256) void xp0_mma_kernel(const int* __restrict__ texts,
                                                      const float* __restrict__ bih0) {
    extern __shared__ char sm[];
    const uint32_t sb = smem_u32_(sm);
    const int tid = threadIdx.x;
    const int wid = tid >> 5;
    const int lane = tid & 31;
    const int n0 = blockIdx.x * 64;
    const int m0 = blockIdx.y * 64;

    for (int idx = tid; idx < 2560; idx += 256) {     // 64 rows * 40 uint4
        const int row = idx / 40, q = idx % 40;
        const int tok = texts[m0 + row];
        *reinterpret_cast<uint4*>(sm + XSM_AH + row * XSTR + 16 * q) =
            reinterpret_cast<const uint4*>(g_ehi + tok * KXP)[q];
        *reinterpret_cast<uint4*>(sm + XSM_AL + row * XSTR + 16 * q) =
            reinterpret_cast<const uint4*>(g_elo + tok * KXP)[q];
        *reinterpret_cast<uint4*>(sm + XSM_BH + row * XSTR + 16 * q) =
            reinterpret_cast<const uint4*>(g_w0hi + (n0 + row) * KXP)[q];
        *reinterpret_cast<uint4*>(sm + XSM_BL + row * XSTR + 16 * q) =
            reinterpret_cast<const uint4*>(g_w0lo + (n0 + row) * KXP)[q];
    }
    __syncthreads();

    const int mg = (wid & 3) * 16;
    const int ng = (wid >> 2) * 32;
    const uint32_t aoff = sb + (uint32_t)((mg + (lane & 15)) * XSTR + (lane >> 4) * 16);
    const uint32_t boff = sb + (uint32_t)((ng + (lane & 7) + ((lane >> 4) << 3)) * XSTR +
                                          ((lane >> 3) & 1) * 16);

    float acc[4][4];
#pragma unroll
    for (int t = 0; t < 4; t++)
#pragma unroll
        for (int j = 0; j < 4; j++) acc[t][j] = 0.0f;

#pragma unroll 4
    for (int ks = 0; ks < KXP / 16; ++ks) {
        uint32_t ah0, ah1, ah2, ah3, al0, al1, al2, al3;
        ldsm4_(ah0, ah1, ah2, ah3, aoff + XSM_AH + ks * 32);
        ldsm4_(al0, al1, al2, al3, aoff + XSM_AL + ks * 32);
        uint32_t bh0, bh1, bh2, bh3, bg0, bg1, bg2, bg3;
        ldsm4_(bh0, bh1, bh2, bh3, boff + XSM_BH + ks * 32);
        ldsm4_(bg0, bg1, bg2, bg3, boff + XSM_BH + 16 * XSTR + ks * 32);
        uint32_t bl0, bl1, bl2, bl3, bm0, bm1, bm2, bm3;
        ldsm4_(bl0, bl1, bl2, bl3, boff + XSM_BL + ks * 32);
        ldsm4_(bm0, bm1, bm2, bm3, boff + XSM_BL + 16 * XSTR + ks * 32);
        mma16816_(acc[0], ah0, ah1, ah2, ah3, bh0, bh1);
        mma16816_(acc[1], ah0, ah1, ah2, ah3, bh2, bh3);
        mma16816_(acc[2], ah0, ah1, ah2, ah3, bg0, bg1);
        mma16816_(acc[3], ah0, ah1, ah2, ah3, bg2, bg3);
        mma16816_(acc[0], al0, al1, al2, al3, bh0, bh1);
        mma16816_(acc[1], al0, al1, al2, al3, bh2, bh3);
        mma16816_(acc[2], al0, al1, al2, al3, bg0, bg1);
        mma16816_(acc[3], al0, al1, al2, al3, bg2, bg3);
        mma16816_(acc[0], ah0, ah1, ah2, ah3, bl0, bl1);
        mma16816_(acc[1], ah0, ah1, ah2, ah3, bl2, bl3);
        mma16816_(acc[2], ah0, ah1, ah2, ah3, bm0, bm1);
        mma16816_(acc[3], ah0, ah1, ah2, ah3, bm2, bm3);
    }

    const int crow = lane >> 2;
    const int ccol = (lane & 3) * 2;
#pragma unroll
    for (int nt = 0; nt < 4; ++nt) {
        const int n = n0 + ng + nt * 8 + ccol;
        const float b0 = bih0[n], b1 = bih0[n + 1];
        const int m = m0 + mg + crow;
        *reinterpret_cast<float2*>(&g_xp0[m * G3 + n]) =
            make_float2(acc[nt][0] + b0, acc[nt][1] + b1);
        *reinterpret_cast<float2*>(&g_xp0[(m + 8) * G3 + n]) =
            make_float2(acc[nt][2] + b0, acc[nt][3] + b1);
    }
}

// =====================================================================
// Persistent recurrence. 144 CTAs = 72 n-tiles(64) x 2 K-halves(256).
// Warp tile 16m x 32n (4 acc chains). A fill = bf16 hi/lo copy.
// Gate fused on CTAs 0..63 (R7-proven mapping), hprev in regs.
// =====================================================================
#define RSTR  528
#define RSM_AH 0
#define RSM_AL (64 * RSTR)
#define RSM_BH (2 * 64 * RSTR)
#define RSM_BL (3 * 64 * RSTR)
#define SMEM_REC (4 * 64 * RSTR)   // 135168

#define LD4_(d, p)  { float4 _t = *reinterpret_cast<const float4*>(p); d[0]=_t.x; d[1]=_t.y; d[2]=_t.z; d[3]=_t.w; }
#define ADD4_(d, p) { float4 _t = *reinterpret_cast<const float4*>(p); d[0]+=_t.x; d[1]+=_t.y; d[2]+=_t.z; d[3]+=_t.w; }

__global__ __launch_bounds__(256) void recurrence_kernel(const float* __restrict__ Whh0,
                                                         const float* __restrict__ Wih1,
                                                         const float* __restrict__ Whh1,
                                                         const float* bhh0,
                                                         const float* bih1,
                                                         const float* bhh1) {
    extern __shared__ char sm[];
    const uint32_t sb = smem_u32_(sm);
    const int tid = threadIdx.x;
    const int wid = tid >> 5;
    const int lane = tid & 31;
    const int cta = blockIdx.x;
    const int nt0 = cta % 72;
    const int kt  = cta / 72;
    const int n0  = nt0 * 64;
    const int k0  = kt * 256;

    const float* W;
    int wr0, cls;
    if (n0 < G3)          { W = Whh0; wr0 = n0;          cls = 0; }
    else if (n0 < 2 * G3) { W = Wih1; wr0 = n0 - G3;     cls = 1; }
    else                  { W = Whh1; wr0 = n0 - 2 * G3; cls = 2; }

    // ---- prologue: weight tile (64 n-rows x 256 k) -> bf16 hi/lo in SMEM ----
    for (int idx = tid; idx < 4096; idx += 256) {   // 64 rows * 64 float4
        const int row = idx >> 6, q = idx & 63;
        float4 v = *reinterpret_cast<const float4*>(W + (wr0 + row) * HDIM + k0 + 4 * q);
        uint2 hi, lo;
        split_hl_(v, hi, lo);
        *reinterpret_cast<uint2*>(sm + RSM_BH + row * RSTR + 8 * q) = hi;
        *reinterpret_cast<uint2*>(sm + RSM_BL + row * RSTR + 8 * q) = lo;
    }

    // ---- static gate assignment: one element-quad per thread (CTAs 0..63) ----
    const int gid = cta * 256 + tid;
    const bool gvalid = gid < 2 * BATCH * HDIM / 4;
    const int glayer = gid >> 13;
    const int gb = (gid >> 7) & 63;
    const int gh4 = (gid & 127) * 4;
    float hp[4] = {0.f, 0.f, 0.f, 0.f};   // persistent h_prev

    // warp geometry: 16m x 32n (4 acc chains)
    const int mg = (wid & 3) * 16;
    const int ng = (wid >> 2) * 32;
    const uint32_t aoff = sb + (uint32_t)((mg + (lane & 15)) * RSTR + (lane >> 4) * 16);
    const uint32_t boff = sb + (uint32_t)((ng + (lane & 7) + ((lane >> 4) << 3)) * RSTR +
                                          ((lane >> 3) & 1) * 16);

    __syncthreads();

    for (int iter = 0; iter <= T_SEQ; ++iter) {
        const bool active = (iter > 0) && !(cls == 0 && iter > 511) && !(cls == 2 && iter < 2);
        if (active) {
            const int tsrc = (cls == 2) ? iter - 2 : iter - 1;
            const __nv_bfloat16* shi = ((cls == 2) ? g_h2hi : g_h1hi) + tsrc * BATCH * HDIM;
            const __nv_bfloat16* slo = ((cls == 2) ? g_h2lo : g_h1lo) + tsrc * BATCH * HDIM;
            // fill A: bf16 copy of the K-half, 64 rows x 256 k (32 uint4/row)
            for (int idx = tid; idx < 2048; idx += 256) {
                const int row = idx >> 5, q = idx & 31;
                *reinterpret_cast<uint4*>(sm + RSM_AH + row * RSTR + 16 * q) =
                    reinterpret_cast<const uint4*>(shi + row * HDIM + k0)[q];
                *reinterpret_cast<uint4*>(sm + RSM_AL + row * RSTR + 16 * q) =
                    reinterpret_cast<const uint4*>(slo + row * HDIM + k0)[q];
            }
            __syncthreads();

            float acc[4][4];
#pragma unroll
            for (int t = 0; t < 4; t++)
#pragma unroll
                for (int j = 0; j < 4; j++) acc[t][j] = 0.0f;

#pragma unroll 8
            for (int ks = 0; ks < 16; ++ks) {
                uint32_t ah0, ah1, ah2, ah3, al0, al1, al2, al3;
                ldsm4_(ah0, ah1, ah2, ah3, aoff + RSM_AH + ks * 32);
                ldsm4_(al0, al1, al2, al3, aoff + RSM_AL + ks * 32);
                uint32_t bh0, bh1, bh2, bh3, bg0, bg1, bg2, bg3;
                ldsm4_(bh0, bh1, bh2, bh3, boff + RSM_BH + ks * 32);
                ldsm4_(bg0, bg1, bg2, bg3, boff + RSM_BH + 16 * RSTR + ks * 32);
                uint32_t bl0, bl1, bl2, bl3, bm0, bm1, bm2, bm3;
                ldsm4_(bl0, bl1, bl2, bl3, boff + RSM_BL + ks * 32);
                ldsm4_(bm0, bm1, bm2, bm3, boff + RSM_BL + 16 * RSTR + ks * 32);
                mma16816_(acc[0], ah0, ah1, ah2, ah3, bh0, bh1);
                mma16816_(acc[1], ah0, ah1, ah2, ah3, bh2, bh3);
                mma16816_(acc[2], ah0, ah1, ah2, ah3, bg0, bg1);
                mma16816_(acc[3], ah0, ah1, ah2, ah3, bg2, bg3);
                mma16816_(acc[0], al0, al1, al2, al3, bh0, bh1);
                mma16816_(acc[1], al0, al1, al2, al3, bh2, bh3);
                mma16816_(acc[2], al0, al1, al2, al3, bg0, bg1);
                mma16816_(acc[3], al0, al1, al2, al3, bg2, bg3);
                mma16816_(acc[0], ah0, ah1, ah2, ah3, bl0, bl1);
                mma16816_(acc[1], ah0, ah1, ah2, ah3, bl2, bl3);
                mma16816_(acc[2], ah0, ah1, ah2, ah3, bm0, bm1);
                mma16816_(acc[3], ah0, ah1, ah2, ah3, bm2, bm3);
            }

            // epilogue: write partials to this K-half's gh buffer
            const int crow = lane >> 2;
            const int ccol = (lane & 3) * 2;
            float* outp = g_gh + kt * BATCH * NCOLS;
#pragma unroll
            for (int nt = 0; nt < 4; ++nt) {
                const int n = n0 + ng + nt * 8 + ccol;
                const int b = mg + crow;
                *reinterpret_cast<float2*>(outp + b * NCOLS + n) =
                    make_float2(acc[nt][0], acc[nt][1]);
                *reinterpret_cast<float2*>(outp + (b + 8) * NCOLS + n) =
                    make_float2(acc[nt][2], acc[nt][3]);
            }
        }
        grid_sync();             // gh partials visible to gate owners

        // ---- fused gate (register-resident hprev; sums both K-halves) ----
        if (gvalid) {
            const float* gha = g_gh + gb * NCOLS;
            const float* ghb = g_gh + BATCH * NCOLS + gb * NCOLS;
            if (glayer == 0) {
                if (iter < T_SEQ) {
                    const float* xp = &g_xp0[(iter * BATCH + gb) * G3];
                    float xr[4], xz[4], xn[4], hr[4], hz[4], hn[4];
                    LD4_(xr, xp + gh4); LD4_(xz, xp + HDIM + gh4); LD4_(xn, xp + 2 * HDIM + gh4);
                    LD4_(hr, bhh0 + gh4); LD4_(hz, bhh0 + HDIM + gh4); LD4_(hn, bhh0 + 2 * HDIM + gh4);
                    if (iter > 0) {
                        ADD4_(hr, gha + gh4);            ADD4_(hr, ghb + gh4);
                        ADD4_(hz, gha + HDIM + gh4);     ADD4_(hz, ghb + HDIM + gh4);
                        ADD4_(hn, gha + 2 * HDIM + gh4); ADD4_(hn, ghb + 2 * HDIM + gh4);
                    }
#pragma unroll
                    for (int j = 0; j < 4; j++) {
                        float r = fsig_(xr[j] + hr[j]);
                        float z = fsig_(xz[j] + hz[j]);
                        float n = ftanh_(xn[j] + r * hn[j]);
                        hp[j] = (1.0f - z) * n + z * hp[j];
                    }
                    uint2 hi, lo;
                    split_hl_(make_float4(hp[0], hp[1], hp[2], hp[3]), hi, lo);
                    const int off = (iter * BATCH + gb) * HDIM + gh4;
                    *reinterpret_cast<uint2*>(&g_h1hi[off]) = hi;
                    *reinterpret_cast<uint2*>(&g_h1lo[off]) = lo;
                }
            } else {
                if (iter >= 1) {
                    const int t = iter - 1;
                    float xr[4], xz[4], xn[4], hr[4], hz[4], hn[4];
                    LD4_(xr, bih1 + gh4); LD4_(xz, bih1 + HDIM + gh4); LD4_(xn, bih1 + 2 * HDIM + gh4);
                    ADD4_(xr, gha + G3 + gh4);            ADD4_(xr, ghb + G3 + gh4);
                    ADD4_(xz, gha + G3 + HDIM + gh4);     ADD4_(xz, ghb + G3 + HDIM + gh4);
                    ADD4_(xn, gha + G3 + 2 * HDIM + gh4); ADD4_(xn, ghb + G3 + 2 * HDIM + gh4);
                    LD4_(hr, bhh1 + gh4); LD4_(hz, bhh1 + HDIM + gh4); LD4_(hn, bhh1 + 2 * HDIM + gh4);
                    if (t > 0) {
                        ADD4_(hr, gha + 2 * G3 + gh4);            ADD4_(hr, ghb + 2 * G3 + gh4);
                        ADD4_(hz, gha + 2 * G3 + HDIM + gh4);     ADD4_(hz, ghb + 2 * G3 + HDIM + gh4);
                        ADD4_(hn, gha + 2 * G3 + 2 * HDIM + gh4); ADD4_(hn, ghb + 2 * G3 + 2 * HDIM + gh4);
                    }
#pragma unroll
                    for (int j = 0; j < 4; j++) {
                        float r = fsig_(xr[j] + hr[j]);
                        float z = fsig_(xz[j] + hz[j]);
                        float n = ftanh_(xn[j] + r * hn[j]);
                        hp[j] = (1.0f - z) * n + z * hp[j];
                    }
                    const int off = (t * BATCH + gb) * HDIM + gh4;
                    *reinterpret_cast<float4*>(&g_h2h[off]) =
                        make_float4(hp[0], hp[1], hp[2], hp[3]);
                    uint2 hi, lo;
                    split_hl_(make_float4(hp[0], hp[1], hp[2], hp[3]), hi, lo);
                    *reinterpret_cast<uint2*>(&g_h2hi[off]) = hi;
                    *reinterpret_cast<uint2*>(&g_h2lo[off]) = lo;
                }
            }
        }
        grid_sync();             // h hi/lo visible to next GEMM
    }
}

// =====================================================================
// pooled[t][h] = mean_b h2[t][b][h];  out[t][l] = pooled . fc_W[l] + fc_b[l]
// =====================================================================
__global__ __launch_bounds__(512) void final_kernel(const float* __restrict__ fc_W,
                                                    const float* __restrict__ fc_b,
                                                    float* __restrict__ out) {
    __shared__ float pooled[HDIM];
    const int t = blockIdx.x;
    const int h = threadIdx.x;

    float s = 0.0f;
    const float* base = &g_h2h[t * BATCH * HDIM + h];
#pragma unroll 8
    for (int b = 0; b < BATCH; ++b) s += base[b * HDIM];
    pooled[h] = s * (1.0f / (float)BATCH);
    __syncthreads();

    const int w = h >> 5, lane = h & 31;
    if (w < 5) {
        float acc = 0.0f;
        for (int k = lane; k < HDIM; k += 32) acc += pooled[k] * fc_W[w * HDIM + k];
#pragma unroll
        for (int o = 16; o > 0; o >>= 1) acc += __shfl_xor_sync(0xFFFFFFFFu, acc, o);
        if (lane == 0) out[t * 5 + w] = acc + fc_b[w];
    }
}

// =====================================================================
extern "C" void kernel_launch(void* const* d_in, const int* in_sizes, int n_in,
                              void* d_out, int out_size) {
    const int*   texts = (const int*)  d_in[0];
    const float* emb   = (const float*)d_in[1];
    const float* Wih0  = (const float*)d_in[2];
    const float* Whh0  = (const float*)d_in[3];
    const float* bih0  = (const float*)d_in[4];
    const float* bhh0  = (const float*)d_in[5];
    const float* Wih1  = (const float*)d_in[6];
    const float* Whh1  = (const float*)d_in[7];
    const float* bih1  = (const float*)d_in[8];
    const float* bhh1  = (const float*)d_in[9];
    const float* fc_W  = (const float*)d_in[10];
    const float* fc_b  = (const float*)d_in[11];
    float* out = (float*)d_out;

    cudaFuncSetAttribute(xp0_mma_kernel,
                         cudaFuncAttributeMaxDynamicSharedMemorySize, SMEM_XP0);
    cudaFuncSetAttribute(recurrence_kernel,
                         cudaFuncAttributeMaxDynamicSharedMemorySize, SMEM_REC);

    prep_kernel<<<(PREP_E + PREP_W + 255) / 256, 256>>>(emb, Wih0);
    xp0_mma_kernel<<<dim3(24, 512), 256, SMEM_XP0>>>(texts, bih0);
    recurrence_kernel<<<NB, 256, SMEM_REC>>>(Whh0, Wih1, Whh1, bhh0, bih1, bhh1);
    final_kernel<<<T_SEQ, 512>>>(fc_W, fc_b, out);
}

// round 11
// speedup vs baseline: 1.6341x; 1.1191x over previous
#include <cuda_runtime.h>
#include <cuda_bf16.h>
#include <cuda_fp16.h>
#include <math.h>
#include <stdint.h>

#define T_SEQ 512
#define BATCH 64
#define HDIM  512
#define EDIM  300
#define G3    1536   // 3*H
#define NCOLS 4608   // 3 * G3
#define NB    144    // 72 n-tiles(64) x 2 k-halves(256), 1 CTA/SM

#define KXP   320    // xp0 K padded (300 -> 320)

// ---------------- device scratch (no allocations) ----------------
__device__ float g_xp0[T_SEQ * BATCH * G3];        // layer-0 input projections
__device__ float g_gh [2 * BATCH * NCOLS];         // split-K partial GEMM outputs
__device__ float g_h2h[T_SEQ * BATCH * HDIM];      // layer-1 fp32 history (for final)
__device__ __half g_h1f[T_SEQ * BATCH * HDIM];     // layer-0 h history, fp16
__device__ __half g_h2f[T_SEQ * BATCH * HDIM];     // layer-1 h history, fp16
__device__ __nv_bfloat16 g_ehi[30000 * KXP];       // emb bf16 hi (K padded w/ zeros)
__device__ __nv_bfloat16 g_elo[30000 * KXP];
__device__ __nv_bfloat16 g_w0hi[G3 * KXP];         // Wih0 bf16 hi
__device__ __nv_bfloat16 g_w0lo[G3 * KXP];
__device__ unsigned g_cnt;
__device__ volatile unsigned g_gen;

// fast transcendentals (MUFU-based; rel err ~1e-6, overflow-safe)
__device__ __forceinline__ float fsig_(float x) { return 1.0f / (1.0f + __expf(-x)); }
__device__ __forceinline__ float ftanh_(float x) {
    float t = __expf(-2.0f * fabsf(x));          // t in (0,1]
    return copysignf(__fdividef(1.0f - t, 1.0f + t), x);
}

// ---------------- warp MMA helpers (sm_80+ PTX: valid on base sm_103) ----------------
__device__ __forceinline__ uint32_t smem_u32_(const void* p) {
    uint32_t a;
    asm("{ .reg .u64 t; cvta.to.shared.u64 t, %1; cvt.u32.u64 %0, t; }" : "=r"(a) : "l"(p));
    return a;
}
__device__ __forceinline__ void ldsm4_(uint32_t& a0, uint32_t& a1, uint32_t& a2,
                                       uint32_t& a3, uint32_t addr) {
    asm volatile("ldmatrix.sync.aligned.m8n8.x4.shared.b16 {%0,%1,%2,%3}, [%4];"
                 : "=r"(a0), "=r"(a1), "=r"(a2), "=r"(a3) : "r"(addr));
}
// bf16 variant (xp0 kernel)
__device__ __forceinline__ void mma16816_(float* c, uint32_t a0, uint32_t a1,
                                          uint32_t a2, uint32_t a3,
                                          uint32_t b0, uint32_t b1) {
    asm volatile("mma.sync.aligned.m16n8k16.row.col.f32.bf16.bf16.f32 "
                 "{%0,%1,%2,%3}, {%4,%5,%6,%7}, {%8,%9}, {%0,%1,%2,%3};"
                 : "+f"(c[0]), "+f"(c[1]), "+f"(c[2]), "+f"(c[3])
                 : "r"(a0), "r"(a1), "r"(a2), "r"(a3), "r"(b0), "r"(b1));
}
// fp16 variant (recurrence)
__device__ __forceinline__ void mma16816h_(float* c, uint32_t a0, uint32_t a1,
                                           uint32_t a2, uint32_t a3,
                                           uint32_t b0, uint32_t b1) {
    asm volatile("mma.sync.aligned.m16n8k16.row.col.f32.f16.f16.f32 "
                 "{%0,%1,%2,%3}, {%4,%5,%6,%7}, {%8,%9}, {%0,%1,%2,%3};"
                 : "+f"(c[0]), "+f"(c[1]), "+f"(c[2]), "+f"(c[3])
                 : "r"(a0), "r"(a1), "r"(a2), "r"(a3), "r"(b0), "r"(b1));
}

// pack fp32x4 -> bf16 hi and lo uint2 (xp0 prep path)
__device__ __forceinline__ void split_hl_(float4 v, uint2& hi, uint2& lo) {
    __nv_bfloat16 h0 = __float2bfloat16(v.x), h1 = __float2bfloat16(v.y);
    __nv_bfloat16 h2 = __float2bfloat16(v.z), h3 = __float2bfloat16(v.w);
    __nv_bfloat16 l0 = __float2bfloat16(v.x - __bfloat162float(h0));
    __nv_bfloat16 l1 = __float2bfloat16(v.y - __bfloat162float(h1));
    __nv_bfloat16 l2 = __float2bfloat16(v.z - __bfloat162float(h2));
    __nv_bfloat16 l3 = __float2bfloat16(v.w - __bfloat162float(h3));
    hi = make_uint2(((uint32_t)__bfloat16_as_ushort(h1) << 16) | __bfloat16_as_ushort(h0),
                    ((uint32_t)__bfloat16_as_ushort(h3) << 16) | __bfloat16_as_ushort(h2));
    lo = make_uint2(((uint32_t)__bfloat16_as_ushort(l1) << 16) | __bfloat16_as_ushort(l0),
                    ((uint32_t)__bfloat16_as_ushort(l3) << 16) | __bfloat16_as_ushort(l2));
}
// pack fp32x4 -> fp16 hi and lo uint2 (recurrence weight prologue)
__device__ __forceinline__ void split_hl_f16_(float4 v, uint2& hi, uint2& lo) {
    __half h0 = __float2half_rn(v.x), h1 = __float2half_rn(v.y);
    __half h2 = __float2half_rn(v.z), h3 = __float2half_rn(v.w);
    __half l0 = __float2half_rn(v.x - __half2float(h0));
    __half l1 = __float2half_rn(v.y - __half2float(h1));
    __half l2 = __float2half_rn(v.z - __half2float(h2));
    __half l3 = __float2half_rn(v.w - __half2float(h3));
    hi = make_uint2(((uint32_t)__half_as_ushort(h1) << 16) | __half_as_ushort(h0),
                    ((uint32_t)__half_as_ushort(h3) << 16) | __half_as_ushort(h2));
    lo = make_uint2(((uint32_t)__half_as_ushort(l1) << 16) | __half_as_ushort(l0),
                    ((uint32_t)__half_as_ushort(l3) << 16) | __half_as_ushort(l2));
}
// pack fp32x4 -> single fp16 uint2 (gate h store)
__device__ __forceinline__ uint2 pack4h_(float4 v) {
    __half h0 = __float2half_rn(v.x), h1 = __float2half_rn(v.y);
    __half h2 = __float2half_rn(v.z), h3 = __float2half_rn(v.w);
    return make_uint2(((uint32_t)__half_as_ushort(h1) << 16) | __half_as_ushort(h0),
                      ((uint32_t)__half_as_ushort(h3) << 16) | __half_as_ushort(h2));
}

// ---------------- flat grid barrier (R7-proven) ----------------
__device__ __forceinline__ void grid_sync() {
    __syncthreads();
    if (threadIdx.x == 0) {
        unsigned old = g_gen;
        __threadfence();
        if (atomicAdd(&g_cnt, 1u) == NB - 1) {
            g_cnt = 0;
            __threadfence();
            g_gen = old + 1;
        } else {
            while (g_gen == old) { __nanosleep(64); }
        }
        __threadfence();
    }
    __syncthreads();
}

// =====================================================================
// prep: fp32 -> bf16 hi/lo for emb (30000x300, pad K to 320) and Wih0 (1536x300)
// =====================================================================
#define PREP_E (30000 * (KXP / 4))
#define PREP_W (G3 * (KXP / 4))
__global__ __launch_bounds__(256) void prep_kernel(const float* __restrict__ emb,
                                                   const float* __restrict__ Wih0) {
    const int id = blockIdx.x * 256 + threadIdx.x;
    if (id < PREP_E) {
        const int row = id / (KXP / 4), q = id % (KXP / 4);
        float4 v = (4 * q + 3 < EDIM)
                       ? *reinterpret_cast<const float4*>(emb + row * EDIM + 4 * q)
                       : make_float4(0.f, 0.f, 0.f, 0.f);
        uint2 hi, lo;
        split_hl_(v, hi, lo);
        *reinterpret_cast<uint2*>(&g_ehi[row * KXP + 4 * q]) = hi;
        *reinterpret_cast<uint2*>(&g_elo[row * KXP + 4 * q]) = lo;
    } else if (id < PREP_E + PREP_W) {
        const int wd = id - PREP_E;
        const int row = wd / (KXP / 4), q = wd % (KXP / 4);
        float4 v = (4 * q + 3 < EDIM)
                       ? *reinterpret_cast<const float4*>(Wih0 + row * EDIM + 4 * q)
                       : make_float4(0.f, 0.f, 0.f, 0.f);
        uint2 hi, lo;
        split_hl_(v, hi, lo);
        *reinterpret_cast<uint2*>(&g_w0hi[row * KXP + 4 * q]) = hi;
        *reinterpret_cast<uint2*>(&g_w0lo[row * KXP + 4 * q]) = lo;
    }
}

// =====================================================================
// xp0 via HMMA bf16 hi/lo: xp0 = emb[texts] @ Wih0^T + bih0  (known-good)
// =====================================================================
#define XSTR  656
#define XSM_AH 0
#define XSM_AL (64 * XSTR)
#define XSM_BH (2 * 64 * XSTR)
#define XSM_BL (3 * 64 * XSTR)
#define SMEM_XP0 (4 * 64 * XSTR)   // 167936

__global__ __launch_bounds__(256) void xp0_mma_kernel(const int* __restrict__ texts,
                                                      const float* __restrict__ bih0) {
    extern __shared__ char sm[];
    const uint32_t sb = smem_u32_(sm);
    const int tid = threadIdx.x;
    const int wid = tid >> 5;
    const int lane = tid & 31;
    const int n0 = blockIdx.x * 64;
    const int m0 = blockIdx.y * 64;

    for (int idx = tid; idx < 2560; idx += 256) {     // 64 rows * 40 uint4
        const int row = idx / 40, q = idx % 40;
        const int tok = texts[m0 + row];
        *reinterpret_cast<uint4*>(sm + XSM_AH + row * XSTR + 16 * q) =
            reinterpret_cast<const uint4*>(g_ehi + tok * KXP)[q];
        *reinterpret_cast<uint4*>(sm + XSM_AL + row * XSTR + 16 * q) =
            reinterpret_cast<const uint4*>(g_elo + tok * KXP)[q];
        *reinterpret_cast<uint4*>(sm + XSM_BH + row * XSTR + 16 * q) =
            reinterpret_cast<const uint4*>(g_w0hi + (n0 + row) * KXP)[q];
        *reinterpret_cast<uint4*>(sm + XSM_BL + row * XSTR + 16 * q) =
            reinterpret_cast<const uint4*>(g_w0lo + (n0 + row) * KXP)[q];
    }
    __syncthreads();

    const int mg = (wid & 3) * 16;
    const int ng = (wid >> 2) * 32;
    const uint32_t aoff = sb + (uint32_t)((mg + (lane & 15)) * XSTR + (lane >> 4) * 16);
    const uint32_t boff = sb + (uint32_t)((ng + (lane & 7) + ((lane >> 4) << 3)) * XSTR +
                                          ((lane >> 3) & 1) * 16);

    float acc[4][4];
#pragma unroll
    for (int t = 0; t < 4; t++)
#pragma unroll
        for (int j = 0; j < 4; j++) acc[t][j] = 0.0f;

#pragma unroll 4
    for (int ks = 0; ks < KXP / 16; ++ks) {
        uint32_t ah0, ah1, ah2, ah3, al0, al1, al2, al3;
        ldsm4_(ah0, ah1, ah2, ah3, aoff + XSM_AH + ks * 32);
        ldsm4_(al0, al1, al2, al3, aoff + XSM_AL + ks * 32);
        uint32_t bh0, bh1, bh2, bh3, bg0, bg1, bg2, bg3;
        ldsm4_(bh0, bh1, bh2, bh3, boff + XSM_BH + ks * 32);
        ldsm4_(bg0, bg1, bg2, bg3, boff + XSM_BH + 16 * XSTR + ks * 32);
        uint32_t bl0, bl1, bl2, bl3, bm0, bm1, bm2, bm3;
        ldsm4_(bl0, bl1, bl2, bl3, boff + XSM_BL + ks * 32);
        ldsm4_(bm0, bm1, bm2, bm3, boff + XSM_BL + 16 * XSTR + ks * 32);
        mma16816_(acc[0], ah0, ah1, ah2, ah3, bh0, bh1);
        mma16816_(acc[1], ah0, ah1, ah2, ah3, bh2, bh3);
        mma16816_(acc[2], ah0, ah1, ah2, ah3, bg0, bg1);
        mma16816_(acc[3], ah0, ah1, ah2, ah3, bg2, bg3);
        mma16816_(acc[0], al0, al1, al2, al3, bh0, bh1);
        mma16816_(acc[1], al0, al1, al2, al3, bh2, bh3);
        mma16816_(acc[2], al0, al1, al2, al3, bg0, bg1);
        mma16816_(acc[3], al0, al1, al2, al3, bg2, bg3);
        mma16816_(acc[0], ah0, ah1, ah2, ah3, bl0, bl1);
        mma16816_(acc[1], ah0, ah1, ah2, ah3, bl2, bl3);
        mma16816_(acc[2], ah0, ah1, ah2, ah3, bm0, bm1);
        mma16816_(acc[3], ah0, ah1, ah2, ah3, bm2, bm3);
    }

    const int crow = lane >> 2;
    const int ccol = (lane & 3) * 2;
#pragma unroll
    for (int nt = 0; nt < 4; ++nt) {
        const int n = n0 + ng + nt * 8 + ccol;
        const float b0 = bih0[n], b1 = bih0[n + 1];
        const int m = m0 + mg + crow;
        *reinterpret_cast<float2*>(&g_xp0[m * G3 + n]) =
            make_float2(acc[nt][0] + b0, acc[nt][1] + b1);
        *reinterpret_cast<float2*>(&g_xp0[(m + 8) * G3 + n]) =
            make_float2(acc[nt][2] + b0, acc[nt][3] + b1);
    }
}

// =====================================================================
// Persistent recurrence. 144 CTAs = 72 n-tiles(64) x 2 K-halves(256).
// fp16 weight-split: D = A * (Wh + Wl), A = fp16(h) single buffer.
// Warp tile 16m x 32n (4 acc chains). Gate on CTAs 0..63, hprev + biases in regs.
// SMEM: A 64 rows | Wh 64 | Wl 64, stride 528B = 101376 B.
// =====================================================================
#define RSTR  528
#define RSM_A  0
#define RSM_WH (64 * RSTR)
#define RSM_WL (2 * 64 * RSTR)
#define SMEM_REC (3 * 64 * RSTR)   // 101376

#define LD4_(d, p)  { float4 _t = *reinterpret_cast<const float4*>(p); d[0]=_t.x; d[1]=_t.y; d[2]=_t.z; d[3]=_t.w; }
#define ADD4_(d, p) { float4 _t = *reinterpret_cast<const float4*>(p); d[0]+=_t.x; d[1]+=_t.y; d[2]+=_t.z; d[3]+=_t.w; }

__global__ __launch_bounds__(256) void recurrence_kernel(const float* __restrict__ Whh0,
                                                         const float* __restrict__ Wih1,
                                                         const float* __restrict__ Whh1,
                                                         const float* bhh0,
                                                         const float* bih1,
                                                         const float* bhh1) {
    extern __shared__ char sm[];
    const uint32_t sb = smem_u32_(sm);
    const int tid = threadIdx.x;
    const int wid = tid >> 5;
    const int lane = tid & 31;
    const int cta = blockIdx.x;
    const int nt0 = cta % 72;
    const int kt  = cta / 72;
    const int n0  = nt0 * 64;
    const int k0  = kt * 256;

    const float* W;
    int wr0, cls;
    if (n0 < G3)          { W = Whh0; wr0 = n0;          cls = 0; }
    else if (n0 < 2 * G3) { W = Wih1; wr0 = n0 - G3;     cls = 1; }
    else                  { W = Whh1; wr0 = n0 - 2 * G3; cls = 2; }

    // ---- prologue: weight tile (64 n-rows x 256 k) -> fp16 hi/lo in SMEM ----
    for (int idx = tid; idx < 4096; idx += 256) {   // 64 rows * 64 float4
        const int row = idx >> 6, q = idx & 63;
        float4 v = *reinterpret_cast<const float4*>(W + (wr0 + row) * HDIM + k0 + 4 * q);
        uint2 hi, lo;
        split_hl_f16_(v, hi, lo);
        *reinterpret_cast<uint2*>(sm + RSM_WH + row * RSTR + 8 * q) = hi;
        *reinterpret_cast<uint2*>(sm + RSM_WL + row * RSTR + 8 * q) = lo;
    }

    // ---- static gate assignment: one element-quad per thread (CTAs 0..63) ----
    const int gid = cta * 256 + tid;
    const bool gvalid = gid < 2 * BATCH * HDIM / 4;
    const int glayer = gid >> 13;
    const int gb = (gid >> 7) & 63;
    const int gh4 = (gid & 127) * 4;
    float hp[4] = {0.f, 0.f, 0.f, 0.f};   // persistent h_prev

    // ---- hoist loop-invariant gate biases into registers ----
    float B1r[4] = {0,0,0,0}, B1z[4] = {0,0,0,0}, B1n[4] = {0,0,0,0};   // hh bias
    float B2r[4] = {0,0,0,0}, B2z[4] = {0,0,0,0}, B2n[4] = {0,0,0,0};   // bih1 (layer1)
    if (gvalid) {
        const float* bh = (glayer == 0) ? bhh0 : bhh1;
        LD4_(B1r, bh + gh4); LD4_(B1z, bh + HDIM + gh4); LD4_(B1n, bh + 2 * HDIM + gh4);
        if (glayer == 1) {
            LD4_(B2r, bih1 + gh4); LD4_(B2z, bih1 + HDIM + gh4); LD4_(B2n, bih1 + 2 * HDIM + gh4);
        }
    }

    // warp geometry: 16m x 32n (4 acc chains)
    const int mg = (wid & 3) * 16;
    const int ng = (wid >> 2) * 32;
    const uint32_t aoff = sb + (uint32_t)((mg + (lane & 15)) * RSTR + (lane >> 4) * 16);
    const uint32_t boff = sb + (uint32_t)((ng + (lane & 7) + ((lane >> 4) << 3)) * RSTR +
                                          ((lane >> 3) & 1) * 16);

    __syncthreads();

    for (int iter = 0; iter <= T_SEQ; ++iter) {
        const bool active = (iter > 0) && !(cls == 0 && iter > 511) && !(cls == 2 && iter < 2);
        if (active) {
            const int tsrc = (cls == 2) ? iter - 2 : iter - 1;
            const __half* hsrc = ((cls == 2) ? g_h2f : g_h1f) + tsrc * BATCH * HDIM;
            // fill A: fp16 copy of the K-half, 64 rows x 256 k
            for (int idx = tid; idx < 2048; idx += 256) {   // 64 rows * 32 uint4
                const int row = idx >> 5, q = idx & 31;
                *reinterpret_cast<uint4*>(sm + RSM_A + row * RSTR + 16 * q) =
                    reinterpret_cast<const uint4*>(hsrc + row * HDIM + k0)[q];
            }
            __syncthreads();

            float acc[4][4];
#pragma unroll
            for (int t = 0; t < 4; t++)
#pragma unroll
                for (int j = 0; j < 4; j++) acc[t][j] = 0.0f;

#pragma unroll 8
            for (int ks = 0; ks < 16; ++ks) {
                uint32_t a0, a1, a2, a3;
                ldsm4_(a0, a1, a2, a3, aoff + RSM_A + ks * 32);
                uint32_t bh0, bh1, bh2, bh3, bg0, bg1, bg2, bg3;
                ldsm4_(bh0, bh1, bh2, bh3, boff + RSM_WH + ks * 32);
                ldsm4_(bg0, bg1, bg2, bg3, boff + RSM_WH + 16 * RSTR + ks * 32);
                uint32_t bl0, bl1, bl2, bl3, bm0, bm1, bm2, bm3;
                ldsm4_(bl0, bl1, bl2, bl3, boff + RSM_WL + ks * 32);
                ldsm4_(bm0, bm1, bm2, bm3, boff + RSM_WL + 16 * RSTR + ks * 32);
                mma16816h_(acc[0], a0, a1, a2, a3, bh0, bh1);
                mma16816h_(acc[1], a0, a1, a2, a3, bh2, bh3);
                mma16816h_(acc[2], a0, a1, a2, a3, bg0, bg1);
                mma16816h_(acc[3], a0, a1, a2, a3, bg2, bg3);
                mma16816h_(acc[0], a0, a1, a2, a3, bl0, bl1);
                mma16816h_(acc[1], a0, a1, a2, a3, bl2, bl3);
                mma16816h_(acc[2], a0, a1, a2, a3, bm0, bm1);
                mma16816h_(acc[3], a0, a1, a2, a3, bm2, bm3);
            }

            // epilogue: write partials to this K-half's gh buffer
            const int crow = lane >> 2;
            const int ccol = (lane & 3) * 2;
            float* outp = g_gh + kt * BATCH * NCOLS;
#pragma unroll
            for (int nt = 0; nt < 4; ++nt) {
                const int n = n0 + ng + nt * 8 + ccol;
                const int b = mg + crow;
                *reinterpret_cast<float2*>(outp + b * NCOLS + n) =
                    make_float2(acc[nt][0], acc[nt][1]);
                *reinterpret_cast<float2*>(outp + (b + 8) * NCOLS + n) =
                    make_float2(acc[nt][2], acc[nt][3]);
            }
        }

        // ---- prefetch xp0 (iteration-known, GEMM-independent) before barrier ----
        float pxr[4], pxz[4], pxn[4];
        if (gvalid && glayer == 0 && iter < T_SEQ) {
            const float* xp = &g_xp0[(iter * BATCH + gb) * G3];
            LD4_(pxr, xp + gh4); LD4_(pxz, xp + HDIM + gh4); LD4_(pxn, xp + 2 * HDIM + gh4);
        }

        grid_sync();             // gh partials visible to gate owners

        // ---- fused gate (register-resident hprev + biases) ----
        if (gvalid) {
            const float* gha = g_gh + gb * NCOLS;
            const float* ghb = g_gh + BATCH * NCOLS + gb * NCOLS;
            if (glayer == 0) {
                if (iter < T_SEQ) {
                    float hr[4], hz[4], hn[4];
#pragma unroll
                    for (int j = 0; j < 4; j++) { hr[j] = B1r[j]; hz[j] = B1z[j]; hn[j] = B1n[j]; }
                    if (iter > 0) {
                        ADD4_(hr, gha + gh4);            ADD4_(hr, ghb + gh4);
                        ADD4_(hz, gha + HDIM + gh4);     ADD4_(hz, ghb + HDIM + gh4);
                        ADD4_(hn, gha + 2 * HDIM + gh4); ADD4_(hn, ghb + 2 * HDIM + gh4);
                    }
#pragma unroll
                    for (int j = 0; j < 4; j++) {
                        float r = fsig_(pxr[j] + hr[j]);
                        float z = fsig_(pxz[j] + hz[j]);
                        float n = ftanh_(pxn[j] + r * hn[j]);
                        hp[j] = (1.0f - z) * n + z * hp[j];
                    }
                    const int off = (iter * BATCH + gb) * HDIM + gh4;
                    *reinterpret_cast<uint2*>(&g_h1f[off]) =
                        pack4h_(make_float4(hp[0], hp[1], hp[2], hp[3]));
                }
            } else {
                if (iter >= 1) {
                    const int t = iter - 1;
                    float xr[4], xz[4], xn[4], hr[4], hz[4], hn[4];
#pragma unroll
                    for (int j = 0; j < 4; j++) {
                        xr[j] = B2r[j]; xz[j] = B2z[j]; xn[j] = B2n[j];
                        hr[j] = B1r[j]; hz[j] = B1z[j]; hn[j] = B1n[j];
                    }
                    ADD4_(xr, gha + G3 + gh4);            ADD4_(xr, ghb + G3 + gh4);
                    ADD4_(xz, gha + G3 + HDIM + gh4);     ADD4_(xz, ghb + G3 + HDIM + gh4);
                    ADD4_(xn, gha + G3 + 2 * HDIM + gh4); ADD4_(xn, ghb + G3 + 2 * HDIM + gh4);
                    if (t > 0) {
                        ADD4_(hr, gha + 2 * G3 + gh4);            ADD4_(hr, ghb + 2 * G3 + gh4);
                        ADD4_(hz, gha + 2 * G3 + HDIM + gh4);     ADD4_(hz, ghb + 2 * G3 + HDIM + gh4);
                        ADD4_(hn, gha + 2 * G3 + 2 * HDIM + gh4); ADD4_(hn, ghb + 2 * G3 + 2 * HDIM + gh4);
                    }
#pragma unroll
                    for (int j = 0; j < 4; j++) {
                        float r = fsig_(xr[j] + hr[j]);
                        float z = fsig_(xz[j] + hz[j]);
                        float n = ftanh_(xn[j] + r * hn[j]);
                        hp[j] = (1.0f - z) * n + z * hp[j];
                    }
                    const int off = (t * BATCH + gb) * HDIM + gh4;
                    *reinterpret_cast<float4*>(&g_h2h[off]) =
                        make_float4(hp[0], hp[1], hp[2], hp[3]);
                    *reinterpret_cast<uint2*>(&g_h2f[off]) =
                        pack4h_(make_float4(hp[0], hp[1], hp[2], hp[3]));
                }
            }
        }
        grid_sync();             // h fp16 visible to next GEMM
    }
}

// =====================================================================
// pooled[t][h] = mean_b h2[t][b][h];  out[t][l] = pooled . fc_W[l] + fc_b[l]
// =====================================================================
__global__ __launch_bounds__(512) void final_kernel(const float* __restrict__ fc_W,
                                                    const float* __restrict__ fc_b,
                                                    float* __restrict__ out) {
    __shared__ float pooled[HDIM];
    const int t = blockIdx.x;
    const int h = threadIdx.x;

    float s = 0.0f;
    const float* base = &g_h2h[t * BATCH * HDIM + h];
#pragma unroll 8
    for (int b = 0; b < BATCH; ++b) s += base[b * HDIM];
    pooled[h] = s * (1.0f / (float)BATCH);
    __syncthreads();

    const int w = h >> 5, lane = h & 31;
    if (w < 5) {
        float acc = 0.0f;
        for (int k = lane; k < HDIM; k += 32) acc += pooled[k] * fc_W[w * HDIM + k];
#pragma unroll
        for (int o = 16; o > 0; o >>= 1) acc += __shfl_xor_sync(0xFFFFFFFFu, acc, o);
        if (lane == 0) out[t * 5 + w] = acc + fc_b[w];
    }
}

// =====================================================================
extern "C" void kernel_launch(void* const* d_in, const int* in_sizes, int n_in,
                              void* d_out, int out_size) {
    const int*   texts = (const int*)  d_in[0];
    const float* emb   = (const float*)d_in[1];
    const float* Wih0  = (const float*)d_in[2];
    const float* Whh0  = (const float*)d_in[3];
    const float* bih0  = (const float*)d_in[4];
    const float* bhh0  = (const float*)d_in[5];
    const float* Wih1  = (const float*)d_in[6];
    const float* Whh1  = (const float*)d_in[7];
    const float* bih1  = (const float*)d_in[8];
    const float* bhh1  = (const float*)d_in[9];
    const float* fc_W  = (const float*)d_in[10];
    const float* fc_b  = (const float*)d_in[11];
    float* out = (float*)d_out;

    cudaFuncSetAttribute(xp0_mma_kernel,
                         cudaFuncAttributeMaxDynamicSharedMemorySize, SMEM_XP0);
    cudaFuncSetAttribute(recurrence_kernel,
                         cudaFuncAttributeMaxDynamicSharedMemorySize, SMEM_REC);

    prep_kernel<<<(PREP_E + PREP_W + 255) / 256, 256>>>(emb, Wih0);
    xp0_mma_kernel<<<dim3(24, 512), 256, SMEM_XP0>>>(texts, bih0);
    recurrence_kernel<<<NB, 256, SMEM_REC>>>(Whh0, Wih1, Whh1, bhh0, bih1, bhh1);
    final_kernel<<<T_SEQ, 512>>>(fc_W, fc_b, out);
}

// round 14
// speedup vs baseline: 1.7331x; 1.0606x over previous
#include <cuda_runtime.h>
#include <cuda_bf16.h>
#include <cuda_fp16.h>
#include <math.h>
#include <stdint.h>

#define T_SEQ 512
#define BATCH 64
#define HDIM  512
#define EDIM  300
#define G3    1536   // 3*H
#define NCOLS 4608   // 3 * G3
#define NB    144    // 72 n-tiles(64) x 2 k-halves(256), 1 CTA/SM

#define KXP   320    // xp0 K padded (300 -> 320)

// ---------------- device scratch (no allocations) ----------------
__device__ float g_xp0[T_SEQ * BATCH * G3];        // layer-0 input projections
__device__ float g_gh [2 * BATCH * NCOLS];         // split-K partial GEMM outputs
__device__ float g_h2h[T_SEQ * BATCH * HDIM];      // layer-1 fp32 history (for final)
__device__ __half g_h1f[T_SEQ * BATCH * HDIM];     // layer-0 h history, fp16
__device__ __half g_h2f[T_SEQ * BATCH * HDIM];     // layer-1 h history, fp16
__device__ __nv_bfloat16 g_ehi[30000 * KXP];       // emb bf16 hi (K padded w/ zeros)
__device__ __nv_bfloat16 g_elo[30000 * KXP];
__device__ __nv_bfloat16 g_w0hi[G3 * KXP];         // Wih0 bf16 hi
__device__ __nv_bfloat16 g_w0lo[G3 * KXP];
__device__ unsigned g_cnt;
__device__ volatile unsigned g_gen;

// fast transcendentals (MUFU-based; rel err ~1e-6, overflow-safe)
__device__ __forceinline__ float fsig_(float x) { return 1.0f / (1.0f + __expf(-x)); }
__device__ __forceinline__ float ftanh_(float x) {
    float t = __expf(-2.0f * fabsf(x));          // t in (0,1]
    return copysignf(__fdividef(1.0f - t, 1.0f + t), x);
}

// ---------------- warp MMA helpers (sm_80+ PTX: valid on base sm_103) ----------------
__device__ __forceinline__ uint32_t smem_u32_(const void* p) {
    uint32_t a;
    asm("{ .reg .u64 t; cvta.to.shared.u64 t, %1; cvt.u32.u64 %0, t; }" : "=r"(a) : "l"(p));
    return a;
}
__device__ __forceinline__ void ldsm4_(uint32_t& a0, uint32_t& a1, uint32_t& a2,
                                       uint32_t& a3, uint32_t addr) {
    asm volatile("ldmatrix.sync.aligned.m8n8.x4.shared.b16 {%0,%1,%2,%3}, [%4];"
                 : "=r"(a0), "=r"(a1), "=r"(a2), "=r"(a3) : "r"(addr));
}
// bf16 variant (xp0 kernel)
__device__ __forceinline__ void mma16816_(float* c, uint32_t a0, uint32_t a1,
                                          uint32_t a2, uint32_t a3,
                                          uint32_t b0, uint32_t b1) {
    asm volatile("mma.sync.aligned.m16n8k16.row.col.f32.bf16.bf16.f32 "
                 "{%0,%1,%2,%3}, {%4,%5,%6,%7}, {%8,%9}, {%0,%1,%2,%3};"
                 : "+f"(c[0]), "+f"(c[1]), "+f"(c[2]), "+f"(c[3])
                 : "r"(a0), "r"(a1), "r"(a2), "r"(a3), "r"(b0), "r"(b1));
}
// fp16 variant (recurrence)
__device__ __forceinline__ void mma16816h_(float* c, uint32_t a0, uint32_t a1,
                                           uint32_t a2, uint32_t a3,
                                           uint32_t b0, uint32_t b1) {
    asm volatile("mma.sync.aligned.m16n8k16.row.col.f32.f16.f16.f32 "
                 "{%0,%1,%2,%3}, {%4,%5,%6,%7}, {%8,%9}, {%0,%1,%2,%3};"
                 : "+f"(c[0]), "+f"(c[1]), "+f"(c[2]), "+f"(c[3])
                 : "r"(a0), "r"(a1), "r"(a2), "r"(a3), "r"(b0), "r"(b1));
}

// pack fp32x4 -> bf16 hi and lo uint2 (xp0 prep path)
__device__ __forceinline__ void split_hl_(float4 v, uint2& hi, uint2& lo) {
    __nv_bfloat16 h0 = __float2bfloat16(v.x), h1 = __float2bfloat16(v.y);
    __nv_bfloat16 h2 = __float2bfloat16(v.z), h3 = __float2bfloat16(v.w);
    __nv_bfloat16 l0 = __float2bfloat16(v.x - __bfloat162float(h0));
    __nv_bfloat16 l1 = __float2bfloat16(v.y - __bfloat162float(h1));
    __nv_bfloat16 l2 = __float2bfloat16(v.z - __bfloat162float(h2));
    __nv_bfloat16 l3 = __float2bfloat16(v.w - __bfloat162float(h3));
    hi = make_uint2(((uint32_t)__bfloat16_as_ushort(h1) << 16) | __bfloat16_as_ushort(h0),
                    ((uint32_t)__bfloat16_as_ushort(h3) << 16) | __bfloat16_as_ushort(h2));
    lo = make_uint2(((uint32_t)__bfloat16_as_ushort(l1) << 16) | __bfloat16_as_ushort(l0),
                    ((uint32_t)__bfloat16_as_ushort(l3) << 16) | __bfloat16_as_ushort(l2));
}
// pack fp32x4 -> single fp16 uint2
__device__ __forceinline__ uint2 pack4h_(float4 v) {
    __half h0 = __float2half_rn(v.x), h1 = __float2half_rn(v.y);
    __half h2 = __float2half_rn(v.z), h3 = __float2half_rn(v.w);
    return make_uint2(((uint32_t)__half_as_ushort(h1) << 16) | __half_as_ushort(h0),
                      ((uint32_t)__half_as_ushort(h3) << 16) | __half_as_ushort(h2));
}

// ---------------- flat grid barrier (R7-proven) ----------------
__device__ __forceinline__ void grid_sync() {
    __syncthreads();
    if (threadIdx.x == 0) {
        unsigned old = g_gen;
        __threadfence();
        if (atomicAdd(&g_cnt, 1u) == NB - 1) {
            g_cnt = 0;
            __threadfence();
            g_gen = old + 1;
        } else {
            while (g_gen == old) { __nanosleep(64); }
        }
        __threadfence();
    }
    __syncthreads();
}

// =====================================================================
// prep: fp32 -> bf16 hi/lo for emb (30000x300, pad K to 320) and Wih0 (1536x300)
// =====================================================================
#define PREP_E (30000 * (KXP / 4))
#define PREP_W (G3 * (KXP / 4))
__global__ __launch_bounds__(256) void prep_kernel(const float* __restrict__ emb,
                                                   const float* __restrict__ Wih0) {
    const int id = blockIdx.x * 256 + threadIdx.x;
    if (id < PREP_E) {
        const int row = id / (KXP / 4), q = id % (KXP / 4);
        float4 v = (4 * q + 3 < EDIM)
                       ? *reinterpret_cast<const float4*>(emb + row * EDIM + 4 * q)
                       : make_float4(0.f, 0.f, 0.f, 0.f);
        uint2 hi, lo;
        split_hl_(v, hi, lo);
        *reinterpret_cast<uint2*>(&g_ehi[row * KXP + 4 * q]) = hi;
        *reinterpret_cast<uint2*>(&g_elo[row * KXP + 4 * q]) = lo;
    } else if (id < PREP_E + PREP_W) {
        const int wd = id - PREP_E;
        const int row = wd / (KXP / 4), q = wd % (KXP / 4);
        float4 v = (4 * q + 3 < EDIM)
                       ? *reinterpret_cast<const float4*>(Wih0 + row * EDIM + 4 * q)
                       : make_float4(0.f, 0.f, 0.f, 0.f);
        uint2 hi, lo;
        split_hl_(v, hi, lo);
        *reinterpret_cast<uint2*>(&g_w0hi[row * KXP + 4 * q]) = hi;
        *reinterpret_cast<uint2*>(&g_w0lo[row * KXP + 4 * q]) = lo;
    }
}

// =====================================================================
// xp0 via HMMA bf16 hi/lo: xp0 = emb[texts] @ Wih0^T + bih0  (known-good)
// =====================================================================
#define XSTR  656
#define XSM_AH 0
#define XSM_AL (64 * XSTR)
#define XSM_BH (2 * 64 * XSTR)
#define XSM_BL (3 * 64 * XSTR)
#define SMEM_XP0 (4 * 64 * XSTR)   // 167936

__global__ __launch_bounds__(256) void xp0_mma_kernel(const int* __restrict__ texts,
                                                      const float* __restrict__ bih0) {
    extern __shared__ char sm[];
    const uint32_t sb = smem_u32_(sm);
    const int tid = threadIdx.x;
    const int wid = tid >> 5;
    const int lane = tid & 31;
    const int n0 = blockIdx.x * 64;
    const int m0 = blockIdx.y * 64;

    for (int idx = tid; idx < 2560; idx += 256) {     // 64 rows * 40 uint4
        const int row = idx / 40, q = idx % 40;
        const int tok = texts[m0 + row];
        *reinterpret_cast<uint4*>(sm + XSM_AH + row * XSTR + 16 * q) =
            reinterpret_cast<const uint4*>(g_ehi + tok * KXP)[q];
        *reinterpret_cast<uint4*>(sm + XSM_AL + row * XSTR + 16 * q) =
            reinterpret_cast<const uint4*>(g_elo + tok * KXP)[q];
        *reinterpret_cast<uint4*>(sm + XSM_BH + row * XSTR + 16 * q) =
            reinterpret_cast<const uint4*>(g_w0hi + (n0 + row) * KXP)[q];
        *reinterpret_cast<uint4*>(sm + XSM_BL + row * XSTR + 16 * q) =
            reinterpret_cast<const uint4*>(g_w0lo + (n0 + row) * KXP)[q];
    }
    __syncthreads();

    const int mg = (wid & 3) * 16;
    const int ng = (wid >> 2) * 32;
    const uint32_t aoff = sb + (uint32_t)((mg + (lane & 15)) * XSTR + (lane >> 4) * 16);
    const uint32_t boff = sb + (uint32_t)((ng + (lane & 7) + ((lane >> 4) << 3)) * XSTR +
                                          ((lane >> 3) & 1) * 16);

    float acc[4][4];
#pragma unroll
    for (int t = 0; t < 4; t++)
#pragma unroll
        for (int j = 0; j < 4; j++) acc[t][j] = 0.0f;

#pragma unroll 4
    for (int ks = 0; ks < KXP / 16; ++ks) {
        uint32_t ah0, ah1, ah2, ah3, al0, al1, al2, al3;
        ldsm4_(ah0, ah1, ah2, ah3, aoff + XSM_AH + ks * 32);
        ldsm4_(al0, al1, al2, al3, aoff + XSM_AL + ks * 32);
        uint32_t bh0, bh1, bh2, bh3, bg0, bg1, bg2, bg3;
        ldsm4_(bh0, bh1, bh2, bh3, boff + XSM_BH + ks * 32);
        ldsm4_(bg0, bg1, bg2, bg3, boff + XSM_BH + 16 * XSTR + ks * 32);
        uint32_t bl0, bl1, bl2, bl3, bm0, bm1, bm2, bm3;
        ldsm4_(bl0, bl1, bl2, bl3, boff + XSM_BL + ks * 32);
        ldsm4_(bm0, bm1, bm2, bm3, boff + XSM_BL + 16 * XSTR + ks * 32);
        mma16816_(acc[0], ah0, ah1, ah2, ah3, bh0, bh1);
        mma16816_(acc[1], ah0, ah1, ah2, ah3, bh2, bh3);
        mma16816_(acc[2], ah0, ah1, ah2, ah3, bg0, bg1);
        mma16816_(acc[3], ah0, ah1, ah2, ah3, bg2, bg3);
        mma16816_(acc[0], al0, al1, al2, al3, bh0, bh1);
        mma16816_(acc[1], al0, al1, al2, al3, bh2, bh3);
        mma16816_(acc[2], al0, al1, al2, al3, bg0, bg1);
        mma16816_(acc[3], al0, al1, al2, al3, bg2, bg3);
        mma16816_(acc[0], ah0, ah1, ah2, ah3, bl0, bl1);
        mma16816_(acc[1], ah0, ah1, ah2, ah3, bl2, bl3);
        mma16816_(acc[2], ah0, ah1, ah2, ah3, bm0, bm1);
        mma16816_(acc[3], ah0, ah1, ah2, ah3, bm2, bm3);
    }

    const int crow = lane >> 2;
    const int ccol = (lane & 3) * 2;
#pragma unroll
    for (int nt = 0; nt < 4; ++nt) {
        const int n = n0 + ng + nt * 8 + ccol;
        const float b0 = bih0[n], b1 = bih0[n + 1];
        const int m = m0 + mg + crow;
        *reinterpret_cast<float2*>(&g_xp0[m * G3 + n]) =
            make_float2(acc[nt][0] + b0, acc[nt][1] + b1);
        *reinterpret_cast<float2*>(&g_xp0[(m + 8) * G3 + n]) =
            make_float2(acc[nt][2] + b0, acc[nt][3] + b1);
    }
}

// =====================================================================
// Persistent recurrence. 144 CTAs = 72 n-tiles(64) x 2 K-halves(256).
// PURE fp16: D = A * W (single pass), A = fp16(h), W = fp16(W).
// Warp tile 16m x 32n (4 acc chains). Gate on CTAs 0..63, hprev + biases in regs.
// SMEM: A 64 rows | W 64 rows, stride 528B = 67584 B.
// =====================================================================
#define RSTR  528
#define RSM_A  0
#define RSM_W  (64 * RSTR)
#define SMEM_REC (2 * 64 * RSTR)   // 67584

#define LD4_(d, p)  { float4 _t = *reinterpret_cast<const float4*>(p); d[0]=_t.x; d[1]=_t.y; d[2]=_t.z; d[3]=_t.w; }
#define ADD4_(d, p) { float4 _t = *reinterpret_cast<const float4*>(p); d[0]+=_t.x; d[1]+=_t.y; d[2]+=_t.z; d[3]+=_t.w; }

__global__ __launch_bounds__(256) void recurrence_kernel(const float* __restrict__ Whh0,
                                                         const float* __restrict__ Wih1,
                                                         const float* __restrict__ Whh1,
                                                         const float* bhh0,
                                                         const float* bih1,
                                                         const float* bhh1) {
    extern __shared__ char sm[];
    const uint32_t sb = smem_u32_(sm);
    const int tid = threadIdx.x;
    const int wid = tid >> 5;
    const int lane = tid & 31;
    const int cta = blockIdx.x;
    const int nt0 = cta % 72;
    const int kt  = cta / 72;
    const int n0  = nt0 * 64;
    const int k0  = kt * 256;

    const float* W;
    int wr0, cls;
    if (n0 < G3)          { W = Whh0; wr0 = n0;          cls = 0; }
    else if (n0 < 2 * G3) { W = Wih1; wr0 = n0 - G3;     cls = 1; }
    else                  { W = Whh1; wr0 = n0 - 2 * G3; cls = 2; }

    // ---- prologue: weight tile (64 n-rows x 256 k) -> fp16 in SMEM ----
    for (int idx = tid; idx < 4096; idx += 256) {   // 64 rows * 64 float4
        const int row = idx >> 6, q = idx & 63;
        float4 v = *reinterpret_cast<const float4*>(W + (wr0 + row) * HDIM + k0 + 4 * q);
        *reinterpret_cast<uint2*>(sm + RSM_W + row * RSTR + 8 * q) = pack4h_(v);
    }

    // ---- static gate assignment: one element-quad per thread (CTAs 0..63) ----
    const int gid = cta * 256 + tid;
    const bool gvalid = gid < 2 * BATCH * HDIM / 4;
    const int glayer = gid >> 13;
    const int gb = (gid >> 7) & 63;
    const int gh4 = (gid & 127) * 4;
    float hp[4] = {0.f, 0.f, 0.f, 0.f};   // persistent h_prev

    // ---- hoist loop-invariant gate biases into registers ----
    float B1r[4] = {0,0,0,0}, B1z[4] = {0,0,0,0}, B1n[4] = {0,0,0,0};   // hh bias
    float B2r[4] = {0,0,0,0}, B2z[4] = {0,0,0,0}, B2n[4] = {0,0,0,0};   // bih1 (layer1)
    if (gvalid) {
        const float* bh = (glayer == 0) ? bhh0 : bhh1;
        LD4_(B1r, bh + gh4); LD4_(B1z, bh + HDIM + gh4); LD4_(B1n, bh + 2 * HDIM + gh4);
        if (glayer == 1) {
            LD4_(B2r, bih1 + gh4); LD4_(B2z, bih1 + HDIM + gh4); LD4_(B2n, bih1 + 2 * HDIM + gh4);
        }
    }

    // warp geometry: 16m x 32n (4 acc chains)
    const int mg = (wid & 3) * 16;
    const int ng = (wid >> 2) * 32;
    const uint32_t aoff = sb + (uint32_t)((mg + (lane & 15)) * RSTR + (lane >> 4) * 16);
    const uint32_t boff = sb + (uint32_t)((ng + (lane & 7) + ((lane >> 4) << 3)) * RSTR +
                                          ((lane >> 3) & 1) * 16);

    __syncthreads();

    for (int iter = 0; iter <= T_SEQ; ++iter) {
        const bool active = (iter > 0) && !(cls == 0 && iter > 511) && !(cls == 2 && iter < 2);
        if (active) {
            const int tsrc = (cls == 2) ? iter - 2 : iter - 1;
            const __half* hsrc = ((cls == 2) ? g_h2f : g_h1f) + tsrc * BATCH * HDIM;
            // fill A: fp16 copy of the K-half, 64 rows x 256 k
            for (int idx = tid; idx < 2048; idx += 256) {   // 64 rows * 32 uint4
                const int row = idx >> 5, q = idx & 31;
                *reinterpret_cast<uint4*>(sm + RSM_A + row * RSTR + 16 * q) =
                    reinterpret_cast<const uint4*>(hsrc + row * HDIM + k0)[q];
            }
            __syncthreads();

            float acc[4][4];
#pragma unroll
            for (int t = 0; t < 4; t++)
#pragma unroll
                for (int j = 0; j < 4; j++) acc[t][j] = 0.0f;

#pragma unroll 8
            for (int ks = 0; ks < 16; ++ks) {
                uint32_t a0, a1, a2, a3;
                ldsm4_(a0, a1, a2, a3, aoff + RSM_A + ks * 32);
                uint32_t b0, b1, b2, b3, c0, c1, c2, c3;
                ldsm4_(b0, b1, b2, b3, boff + RSM_W + ks * 32);
                ldsm4_(c0, c1, c2, c3, boff + RSM_W + 16 * RSTR + ks * 32);
                mma16816h_(acc[0], a0, a1, a2, a3, b0, b1);
                mma16816h_(acc[1], a0, a1, a2, a3, b2, b3);
                mma16816h_(acc[2], a0, a1, a2, a3, c0, c1);
                mma16816h_(acc[3], a0, a1, a2, a3, c2, c3);
            }

            // epilogue: write partials to this K-half's gh buffer
            const int crow = lane >> 2;
            const int ccol = (lane & 3) * 2;
            float* outp = g_gh + kt * BATCH * NCOLS;
#pragma unroll
            for (int nt = 0; nt < 4; ++nt) {
                const int n = n0 + ng + nt * 8 + ccol;
                const int b = mg + crow;
                *reinterpret_cast<float2*>(outp + b * NCOLS + n) =
                    make_float2(acc[nt][0], acc[nt][1]);
                *reinterpret_cast<float2*>(outp + (b + 8) * NCOLS + n) =
                    make_float2(acc[nt][2], acc[nt][3]);
            }
        }

        // ---- prefetch xp0 (iteration-known, GEMM-independent) before barrier ----
        float pxr[4], pxz[4], pxn[4];
        if (gvalid && glayer == 0 && iter < T_SEQ) {
            const float* xp = &g_xp0[(iter * BATCH + gb) * G3];
            LD4_(pxr, xp + gh4); LD4_(pxz, xp + HDIM + gh4); LD4_(pxn, xp + 2 * HDIM + gh4);
        }

        grid_sync();             // gh partials visible to gate owners

        // ---- fused gate (register-resident hprev + biases) ----
        if (gvalid) {
            const float* gha = g_gh + gb * NCOLS;
            const float* ghb = g_gh + BATCH * NCOLS + gb * NCOLS;
            if (glayer == 0) {
                if (iter < T_SEQ) {
                    float hr[4], hz[4], hn[4];
#pragma unroll
                    for (int j = 0; j < 4; j++) { hr[j] = B1r[j]; hz[j] = B1z[j]; hn[j] = B1n[j]; }
                    if (iter > 0) {
                        ADD4_(hr, gha + gh4);            ADD4_(hr, ghb + gh4);
                        ADD4_(hz, gha + HDIM + gh4);     ADD4_(hz, ghb + HDIM + gh4);
                        ADD4_(hn, gha + 2 * HDIM + gh4); ADD4_(hn, ghb + 2 * HDIM + gh4);
                    }
#pragma unroll
                    for (int j = 0; j < 4; j++) {
                        float r = fsig_(pxr[j] + hr[j]);
                        float z = fsig_(pxz[j] + hz[j]);
                        float n = ftanh_(pxn[j] + r * hn[j]);
                        hp[j] = (1.0f - z) * n + z * hp[j];
                    }
                    const int off = (iter * BATCH + gb) * HDIM + gh4;
                    *reinterpret_cast<uint2*>(&g_h1f[off]) =
                        pack4h_(make_float4(hp[0], hp[1], hp[2], hp[3]));
                }
            } else {
                if (iter >= 1) {
                    const int t = iter - 1;
                    float xr[4], xz[4], xn[4], hr[4], hz[4], hn[4];
#pragma unroll
                    for (int j = 0; j < 4; j++) {
                        xr[j] = B2r[j]; xz[j] = B2z[j]; xn[j] = B2n[j];
                        hr[j] = B1r[j]; hz[j] = B1z[j]; hn[j] = B1n[j];
                    }
                    ADD4_(xr, gha + G3 + gh4);            ADD4_(xr, ghb + G3 + gh4);
                    ADD4_(xz, gha + G3 + HDIM + gh4);     ADD4_(xz, ghb + G3 + HDIM + gh4);
                    ADD4_(xn, gha + G3 + 2 * HDIM + gh4); ADD4_(xn, ghb + G3 + 2 * HDIM + gh4);
                    if (t > 0) {
                        ADD4_(hr, gha + 2 * G3 + gh4);            ADD4_(hr, ghb + 2 * G3 + gh4);
                        ADD4_(hz, gha + 2 * G3 + HDIM + gh4);     ADD4_(hz, ghb + 2 * G3 + HDIM + gh4);
                        ADD4_(hn, gha + 2 * G3 + 2 * HDIM + gh4); ADD4_(hn, ghb + 2 * G3 + 2 * HDIM + gh4);
                    }
#pragma unroll
                    for (int j = 0; j < 4; j++) {
                        float r = fsig_(xr[j] + hr[j]);
                        float z = fsig_(xz[j] + hz[j]);
                        float n = ftanh_(xn[j] + r * hn[j]);
                        hp[j] = (1.0f - z) * n + z * hp[j];
                    }
                    const int off = (t * BATCH + gb) * HDIM + gh4;
                    *reinterpret_cast<float4*>(&g_h2h[off]) =
                        make_float4(hp[0], hp[1], hp[2], hp[3]);
                    *reinterpret_cast<uint2*>(&g_h2f[off]) =
                        pack4h_(make_float4(hp[0], hp[1], hp[2], hp[3]));
                }
            }
        }
        grid_sync();             // h fp16 visible to next GEMM
    }
}

// =====================================================================
// pooled[t][h] = mean_b h2[t][b][h];  out[t][l] = pooled . fc_W[l] + fc_b[l]
// =====================================================================
__global__ __launch_bounds__(512) void final_kernel(const float* __restrict__ fc_W,
                                                    const float* __restrict__ fc_b,
                                                    float* __restrict__ out) {
    __shared__ float pooled[HDIM];
    const int t = blockIdx.x;
    const int h = threadIdx.x;

    float s = 0.0f;
    const float* base = &g_h2h[t * BATCH * HDIM + h];
#pragma unroll 8
    for (int b = 0; b < BATCH; ++b) s += base[b * HDIM];
    pooled[h] = s * (1.0f / (float)BATCH);
    __syncthreads();

    const int w = h >> 5, lane = h & 31;
    if (w < 5) {
        float acc = 0.0f;
        for (int k = lane; k < HDIM; k += 32) acc += pooled[k] * fc_W[w * HDIM + k];
#pragma unroll
        for (int o = 16; o > 0; o >>= 1) acc += __shfl_xor_sync(0xFFFFFFFFu, acc, o);
        if (lane == 0) out[t * 5 + w] = acc + fc_b[w];
    }
}

// =====================================================================
extern "C" void kernel_launch(void* const* d_in, const int* in_sizes, int n_in,
                              void* d_out, int out_size) {
    const int*   texts = (const int*)  d_in[0];
    const float* emb   = (const float*)d_in[1];
    const float* Wih0  = (const float*)d_in[2];
    const float* Whh0  = (const float*)d_in[3];
    const float* bih0  = (const float*)d_in[4];
    const float* bhh0  = (const float*)d_in[5];
    const float* Wih1  = (const float*)d_in[6];
    const float* Whh1  = (const float*)d_in[7];
    const float* bih1  = (const float*)d_in[8];
    const float* bhh1  = (const float*)d_in[9];
    const float* fc_W  = (const float*)d_in[10];
    const float* fc_b  = (const float*)d_in[11];
    float* out = (float*)d_out;

    cudaFuncSetAttribute(xp0_mma_kernel,
                         cudaFuncAttributeMaxDynamicSharedMemorySize, SMEM_XP0);
    cudaFuncSetAttribute(recurrence_kernel,
                         cudaFuncAttributeMaxDynamicSharedMemorySize, SMEM_REC);

    prep_kernel<<<(PREP_E + PREP_W + 255) / 256, 256>>>(emb, Wih0);
    xp0_mma_kernel<<<dim3(24, 512), 256, SMEM_XP0>>>(texts, bih0);
    recurrence_kernel<<<NB, 256, SMEM_REC>>>(Whh0, Wih1, Whh1, bhh0, bih1, bhh1);
    final_kernel<<<T_SEQ, 512>>>(fc_W, fc_b, out);
}

// round 16
// speedup vs baseline: 2.0287x; 1.1706x over previous
#include <cuda_runtime.h>
#include <cuda_bf16.h>
#include <cuda_fp16.h>
#include <math.h>
#include <stdint.h>

#define T_SEQ 512
#define BATCH 64
#define HDIM  512
#define EDIM  300
#define G3    1536   // 3*H
#define NCOLS 4608   // 3 * G3
#define NB    144    // 72 n-tiles(64) x 2 k-halves(256), 1 CTA/SM
#define NGATE 64     // CTAs that run the gate

#define KXP   320    // xp0 K padded (300 -> 320)

// ---------------- device scratch (no allocations) ----------------
__device__ float g_xp0[T_SEQ * BATCH * G3];        // layer-0 input projections
__device__ float g_gh [4 * BATCH * NCOLS];         // [parity][kt][b][col] double-buffered split-K
__device__ float g_h2h[T_SEQ * BATCH * HDIM];      // layer-1 fp32 history (for final)
__device__ __half g_h1f[T_SEQ * BATCH * HDIM];     // layer-0 h history, fp16
__device__ __half g_h2f[T_SEQ * BATCH * HDIM];     // layer-1 h history, fp16
__device__ __nv_bfloat16 g_ehi[30000 * KXP];       // emb bf16 hi (K padded w/ zeros)
__device__ __nv_bfloat16 g_elo[30000 * KXP];
__device__ __nv_bfloat16 g_w0hi[G3 * KXP];         // Wih0 bf16 hi
__device__ __nv_bfloat16 g_w0lo[G3 * KXP];
__device__ unsigned g_ghdone;                      // monotonic: 144 arrivals / iter
__device__ unsigned g_hdone;                       // monotonic: 64 arrivals / iter

// fast transcendentals (MUFU-based; rel err ~1e-6, overflow-safe)
__device__ __forceinline__ float fsig_(float x) { return 1.0f / (1.0f + __expf(-x)); }
__device__ __forceinline__ float ftanh_(float x) {
    float t = __expf(-2.0f * fabsf(x));          // t in (0,1]
    return copysignf(__fdividef(1.0f - t, 1.0f + t), x);
}

// ---------------- warp MMA helpers (sm_80+ PTX: valid on base sm_103) ----------------
__device__ __forceinline__ uint32_t smem_u32_(const void* p) {
    uint32_t a;
    asm("{ .reg .u64 t; cvta.to.shared.u64 t, %1; cvt.u32.u64 %0, t; }" : "=r"(a) : "l"(p));
    return a;
}
__device__ __forceinline__ void ldsm4_(uint32_t& a0, uint32_t& a1, uint32_t& a2,
                                       uint32_t& a3, uint32_t addr) {
    asm volatile("ldmatrix.sync.aligned.m8n8.x4.shared.b16 {%0,%1,%2,%3}, [%4];"
                 : "=r"(a0), "=r"(a1), "=r"(a2), "=r"(a3) : "r"(addr));
}
// bf16 variant (xp0 kernel)
__device__ __forceinline__ void mma16816_(float* c, uint32_t a0, uint32_t a1,
                                          uint32_t a2, uint32_t a3,
                                          uint32_t b0, uint32_t b1) {
    asm volatile("mma.sync.aligned.m16n8k16.row.col.f32.bf16.bf16.f32 "
                 "{%0,%1,%2,%3}, {%4,%5,%6,%7}, {%8,%9}, {%0,%1,%2,%3};"
                 : "+f"(c[0]), "+f"(c[1]), "+f"(c[2]), "+f"(c[3])
                 : "r"(a0), "r"(a1), "r"(a2), "r"(a3), "r"(b0), "r"(b1));
}
// fp16 variant (recurrence)
__device__ __forceinline__ void mma16816h_(float* c, uint32_t a0, uint32_t a1,
                                           uint32_t a2, uint32_t a3,
                                           uint32_t b0, uint32_t b1) {
    asm volatile("mma.sync.aligned.m16n8k16.row.col.f32.f16.f16.f32 "
                 "{%0,%1,%2,%3}, {%4,%5,%6,%7}, {%8,%9}, {%0,%1,%2,%3};"
                 : "+f"(c[0]), "+f"(c[1]), "+f"(c[2]), "+f"(c[3])
                 : "r"(a0), "r"(a1), "r"(a2), "r"(a3), "r"(b0), "r"(b1));
}

// pack fp32x4 -> bf16 hi and lo uint2 (xp0 prep path)
__device__ __forceinline__ void split_hl_(float4 v, uint2& hi, uint2& lo) {
    __nv_bfloat16 h0 = __float2bfloat16(v.x), h1 = __float2bfloat16(v.y);
    __nv_bfloat16 h2 = __float2bfloat16(v.z), h3 = __float2bfloat16(v.w);
    __nv_bfloat16 l0 = __float2bfloat16(v.x - __bfloat162float(h0));
    __nv_bfloat16 l1 = __float2bfloat16(v.y - __bfloat162float(h1));
    __nv_bfloat16 l2 = __float2bfloat16(v.z - __bfloat162float(h2));
    __nv_bfloat16 l3 = __float2bfloat16(v.w - __bfloat162float(h3));
    hi = make_uint2(((uint32_t)__bfloat16_as_ushort(h1) << 16) | __bfloat16_as_ushort(h0),
                    ((uint32_t)__bfloat16_as_ushort(h3) << 16) | __bfloat16_as_ushort(h2));
    lo = make_uint2(((uint32_t)__bfloat16_as_ushort(l1) << 16) | __bfloat16_as_ushort(l0),
                    ((uint32_t)__bfloat16_as_ushort(l3) << 16) | __bfloat16_as_ushort(l2));
}
// pack fp32x4 -> single fp16 uint2
__device__ __forceinline__ uint2 pack4h_(float4 v) {
    __half h0 = __float2half_rn(v.x), h1 = __float2half_rn(v.y);
    __half h2 = __float2half_rn(v.z), h3 = __float2half_rn(v.w);
    return make_uint2(((uint32_t)__half_as_ushort(h1) << 16) | __half_as_ushort(h0),
                      ((uint32_t)__half_as_ushort(h3) << 16) | __half_as_ushort(h2));
}

// ---------------- one-sided flag sync ----------------
// consumer: spin until *ctr >= target, then acquire-fence + CTA sync
__device__ __forceinline__ void wait_ge_(unsigned* ctr, unsigned target) {
    if (threadIdx.x == 0) {
        while (*(volatile unsigned*)ctr < target) { __nanosleep(64); }
        __threadfence();
    }
    __syncthreads();
}
// producer: CTA sync, release-fence + arrive
__device__ __forceinline__ void arrive_(unsigned* ctr) {
    __syncthreads();
    if (threadIdx.x == 0) {
        __threadfence();
        atomicAdd(ctr, 1u);
    }
}

// =====================================================================
// prep: fp32 -> bf16 hi/lo for emb (30000x300, pad K to 320) and Wih0 (1536x300)
// =====================================================================
#define PREP_E (30000 * (KXP / 4))
#define PREP_W (G3 * (KXP / 4))
__global__ __launch_bounds__(256) void prep_kernel(const float* __restrict__ emb,
                                                   const float* __restrict__ Wih0) {
    const int id = blockIdx.x * 256 + threadIdx.x;
    if (id < PREP_E) {
        const int row = id / (KXP / 4), q = id % (KXP / 4);
        float4 v = (4 * q + 3 < EDIM)
                       ? *reinterpret_cast<const float4*>(emb + row * EDIM + 4 * q)
                       : make_float4(0.f, 0.f, 0.f, 0.f);
        uint2 hi, lo;
        split_hl_(v, hi, lo);
        *reinterpret_cast<uint2*>(&g_ehi[row * KXP + 4 * q]) = hi;
        *reinterpret_cast<uint2*>(&g_elo[row * KXP + 4 * q]) = lo;
    } else if (id < PREP_E + PREP_W) {
        const int wd = id - PREP_E;
        const int row = wd / (KXP / 4), q = wd % (KXP / 4);
        float4 v = (4 * q + 3 < EDIM)
                       ? *reinterpret_cast<const float4*>(Wih0 + row * EDIM + 4 * q)
                       : make_float4(0.f, 0.f, 0.f, 0.f);
        uint2 hi, lo;
        split_hl_(v, hi, lo);
        *reinterpret_cast<uint2*>(&g_w0hi[row * KXP + 4 * q]) = hi;
        *reinterpret_cast<uint2*>(&g_w0lo[row * KXP + 4 * q]) = lo;
    }
}

// =====================================================================
// xp0 via HMMA bf16 hi/lo: xp0 = emb[texts] @ Wih0^T + bih0  (known-good)
// =====================================================================
#define XSTR  656
#define XSM_AH 0
#define XSM_AL (64 * XSTR)
#define XSM_BH (2 * 64 * XSTR)
#define XSM_BL (3 * 64 * XSTR)
#define SMEM_XP0 (4 * 64 * XSTR)   // 167936

__global__ __launch_bounds__(256) void xp0_mma_kernel(const int* __restrict__ texts,
                                                      const float* __restrict__ bih0) {
    extern __shared__ char sm[];
    const uint32_t sb = smem_u32_(sm);
    const int tid = threadIdx.x;
    const int wid = tid >> 5;
    const int lane = tid & 31;
    const int n0 = blockIdx.x * 64;
    const int m0 = blockIdx.y * 64;

    for (int idx = tid; idx < 2560; idx += 256) {     // 64 rows * 40 uint4
        const int row = idx / 40, q = idx % 40;
        const int tok = texts[m0 + row];
        *reinterpret_cast<uint4*>(sm + XSM_AH + row * XSTR + 16 * q) =
            reinterpret_cast<const uint4*>(g_ehi + tok * KXP)[q];
        *reinterpret_cast<uint4*>(sm + XSM_AL + row * XSTR + 16 * q) =
            reinterpret_cast<const uint4*>(g_elo + tok * KXP)[q];
        *reinterpret_cast<uint4*>(sm + XSM_BH + row * XSTR + 16 * q) =
            reinterpret_cast<const uint4*>(g_w0hi + (n0 + row) * KXP)[q];
        *reinterpret_cast<uint4*>(sm + XSM_BL + row * XSTR + 16 * q) =
            reinterpret_cast<const uint4*>(g_w0lo + (n0 + row) * KXP)[q];
    }
    __syncthreads();

    const int mg = (wid & 3) * 16;
    const int ng = (wid >> 2) * 32;
    const uint32_t aoff = sb + (uint32_t)((mg + (lane & 15)) * XSTR + (lane >> 4) * 16);
    const uint32_t boff = sb + (uint32_t)((ng + (lane & 7) + ((lane >> 4) << 3)) * XSTR +
                                          ((lane >> 3) & 1) * 16);

    float acc[4][4];
#pragma unroll
    for (int t = 0; t < 4; t++)
#pragma unroll
        for (int j = 0; j < 4; j++) acc[t][j] = 0.0f;

#pragma unroll 4
    for (int ks = 0; ks < KXP / 16; ++ks) {
        uint32_t ah0, ah1, ah2, ah3, al0, al1, al2, al3;
        ldsm4_(ah0, ah1, ah2, ah3, aoff + XSM_AH + ks * 32);
        ldsm4_(al0, al1, al2, al3, aoff + XSM_AL + ks * 32);
        uint32_t bh0, bh1, bh2, bh3, bg0, bg1, bg2, bg3;
        ldsm4_(bh0, bh1, bh2, bh3, boff + XSM_BH + ks * 32);
        ldsm4_(bg0, bg1, bg2, bg3, boff + XSM_BH + 16 * XSTR + ks * 32);
        uint32_t bl0, bl1, bl2, bl3, bm0, bm1, bm2, bm3;
        ldsm4_(bl0, bl1, bl2, bl3, boff + XSM_BL + ks * 32);
        ldsm4_(bm0, bm1, bm2, bm3, boff + XSM_BL + 16 * XSTR + ks * 32);
        mma16816_(acc[0], ah0, ah1, ah2, ah3, bh0, bh1);
        mma16816_(acc[1], ah0, ah1, ah2, ah3, bh2, bh3);
        mma16816_(acc[2], ah0, ah1, ah2, ah3, bg0, bg1);
        mma16816_(acc[3], ah0, ah1, ah2, ah3, bg2, bg3);
        mma16816_(acc[0], al0, al1, al2, al3, bh0, bh1);
        mma16816_(acc[1], al0, al1, al2, al3, bh2, bh3);
        mma16816_(acc[2], al0, al1, al2, al3, bg0, bg1);
        mma16816_(acc[3], al0, al1, al2, al3, bg2, bg3);
        mma16816_(acc[0], ah0, ah1, ah2, ah3, bl0, bl1);
        mma16816_(acc[1], ah0, ah1, ah2, ah3, bl2, bl3);
        mma16816_(acc[2], ah0, ah1, ah2, ah3, bm0, bm1);
        mma16816_(acc[3], ah0, ah1, ah2, ah3, bm2, bm3);
    }

    const int crow = lane >> 2;
    const int ccol = (lane & 3) * 2;
#pragma unroll
    for (int nt = 0; nt < 4; ++nt) {
        const int n = n0 + ng + nt * 8 + ccol;
        const float b0 = bih0[n], b1 = bih0[n + 1];
        const int m = m0 + mg + crow;
        *reinterpret_cast<float2*>(&g_xp0[m * G3 + n]) =
            make_float2(acc[nt][0] + b0, acc[nt][1] + b1);
        *reinterpret_cast<float2*>(&g_xp0[(m + 8) * G3 + n]) =
            make_float2(acc[nt][2] + b0, acc[nt][3] + b1);
    }
}

// =====================================================================
// Persistent recurrence with one-sided flag sync.
// 144 CTAs = 72 n-tiles(64) x 2 K-halves(256). Pure fp16 GEMM (R14-proven).
// gh double-buffered by iter parity. Gate on CTAs 0..63.
// =====================================================================
#define RSTR  528
#define RSM_A  0
#define RSM_W  (64 * RSTR)
#define SMEM_REC (2 * 64 * RSTR)   // 67584

#define LD4_(d, p)  { float4 _t = *reinterpret_cast<const float4*>(p); d[0]=_t.x; d[1]=_t.y; d[2]=_t.z; d[3]=_t.w; }
#define ADD4_(d, p) { float4 _t = *reinterpret_cast<const float4*>(p); d[0]+=_t.x; d[1]+=_t.y; d[2]+=_t.z; d[3]+=_t.w; }

__global__ __launch_bounds__(256) void recurrence_kernel(const float* __restrict__ Whh0,
                                                         const float* __restrict__ Wih1,
                                                         const float* __restrict__ Whh1,
                                                         const float* bhh0,
                                                         const float* bih1,
                                                         const float* bhh1) {
    extern __shared__ char sm[];
    const uint32_t sb = smem_u32_(sm);
    const int tid = threadIdx.x;
    const int wid = tid >> 5;
    const int lane = tid & 31;
    const int cta = blockIdx.x;
    const int nt0 = cta % 72;
    const int kt  = cta / 72;
    const int n0  = nt0 * 64;
    const int k0  = kt * 256;

    const float* W;
    int wr0, cls;
    if (n0 < G3)          { W = Whh0; wr0 = n0;          cls = 0; }
    else if (n0 < 2 * G3) { W = Wih1; wr0 = n0 - G3;     cls = 1; }
    else                  { W = Whh1; wr0 = n0 - 2 * G3; cls = 2; }

    // ---- prologue: weight tile (64 n-rows x 256 k) -> fp16 in SMEM ----
    for (int idx = tid; idx < 4096; idx += 256) {   // 64 rows * 64 float4
        const int row = idx >> 6, q = idx & 63;
        float4 v = *reinterpret_cast<const float4*>(W + (wr0 + row) * HDIM + k0 + 4 * q);
        *reinterpret_cast<uint2*>(sm + RSM_W + row * RSTR + 8 * q) = pack4h_(v);
    }

    // ---- static gate assignment: one element-quad per thread (CTAs 0..63) ----
    const int gid = cta * 256 + tid;
    const bool gcta = cta < NGATE;
    const bool gvalid = gid < 2 * BATCH * HDIM / 4;
    const int glayer = gid >> 13;
    const int gb = (gid >> 7) & 63;
    const int gh4 = (gid & 127) * 4;
    float hp[4] = {0.f, 0.f, 0.f, 0.f};   // persistent h_prev

    // ---- hoist loop-invariant gate biases into registers ----
    float B1r[4] = {0,0,0,0}, B1z[4] = {0,0,0,0}, B1n[4] = {0,0,0,0};   // hh bias
    float B2r[4] = {0,0,0,0}, B2z[4] = {0,0,0,0}, B2n[4] = {0,0,0,0};   // bih1 (layer1)
    if (gvalid) {
        const float* bh = (glayer == 0) ? bhh0 : bhh1;
        LD4_(B1r, bh + gh4); LD4_(B1z, bh + HDIM + gh4); LD4_(B1n, bh + 2 * HDIM + gh4);
        if (glayer == 1) {
            LD4_(B2r, bih1 + gh4); LD4_(B2z, bih1 + HDIM + gh4); LD4_(B2n, bih1 + 2 * HDIM + gh4);
        }
    }

    // warp geometry: 16m x 32n (4 acc chains)
    const int mg = (wid & 3) * 16;
    const int ng = (wid >> 2) * 32;
    const uint32_t aoff = sb + (uint32_t)((mg + (lane & 15)) * RSTR + (lane >> 4) * 16);
    const uint32_t boff = sb + (uint32_t)((ng + (lane & 7) + ((lane >> 4) << 3)) * RSTR +
                                          ((lane >> 3) & 1) * 16);

    __syncthreads();

    for (int iter = 0; iter <= T_SEQ; ++iter) {
        const bool active = (iter > 0) && !(cls == 0 && iter > 511) && !(cls == 2 && iter < 2);
        if (active) {
            // wait until gate iterations 0..iter-1 complete (h history ready)
            wait_ge_(&g_hdone, (unsigned)(NGATE * iter));

            const int tsrc = (cls == 2) ? iter - 2 : iter - 1;
            const __half* hsrc = ((cls == 2) ? g_h2f : g_h1f) + tsrc * BATCH * HDIM;
            // fill A: fp16 copy of the K-half, 64 rows x 256 k
            for (int idx = tid; idx < 2048; idx += 256) {   // 64 rows * 32 uint4
                const int row = idx >> 5, q = idx & 31;
                *reinterpret_cast<uint4*>(sm + RSM_A + row * RSTR + 16 * q) =
                    reinterpret_cast<const uint4*>(hsrc + row * HDIM + k0)[q];
            }
            __syncthreads();

            float acc[4][4];
#pragma unroll
            for (int t = 0; t < 4; t++)
#pragma unroll
                for (int j = 0; j < 4; j++) acc[t][j] = 0.0f;

#pragma unroll 8
            for (int ks = 0; ks < 16; ++ks) {
                uint32_t a0, a1, a2, a3;
                ldsm4_(a0, a1, a2, a3, aoff + RSM_A + ks * 32);
                uint32_t b0, b1, b2, b3, c0, c1, c2, c3;
                ldsm4_(b0, b1, b2, b3, boff + RSM_W + ks * 32);
                ldsm4_(c0, c1, c2, c3, boff + RSM_W + 16 * RSTR + ks * 32);
                mma16816h_(acc[0], a0, a1, a2, a3, b0, b1);
                mma16816h_(acc[1], a0, a1, a2, a3, b2, b3);
                mma16816h_(acc[2], a0, a1, a2, a3, c0, c1);
                mma16816h_(acc[3], a0, a1, a2, a3, c2, c3);
            }

            // epilogue: write partials to this iter-parity / K-half gh buffer
            const int crow = lane >> 2;
            const int ccol = (lane & 3) * 2;
            float* outp = g_gh + ((iter & 1) * 2 + kt) * BATCH * NCOLS;
#pragma unroll
            for (int nt = 0; nt < 4; ++nt) {
                const int n = n0 + ng + nt * 8 + ccol;
                const int b = mg + crow;
                *reinterpret_cast<float2*>(outp + b * NCOLS + n) =
                    make_float2(acc[nt][0], acc[nt][1]);
                *reinterpret_cast<float2*>(outp + (b + 8) * NCOLS + n) =
                    make_float2(acc[nt][2], acc[nt][3]);
            }
        }
        arrive_(&g_ghdone);      // one arrival per CTA per iteration (active or not)

        if (gcta) {
            // ---- prefetch xp0 (iteration-known) before the gh wait ----
            float pxr[4], pxz[4], pxn[4];
            if (gvalid && glayer == 0 && iter < T_SEQ) {
                const float* xp = &g_xp0[(iter * BATCH + gb) * G3];
                LD4_(pxr, xp + gh4); LD4_(pxz, xp + HDIM + gh4); LD4_(pxn, xp + 2 * HDIM + gh4);
            }

            // wait for ALL CTAs' gh of this iteration
            wait_ge_(&g_ghdone, (unsigned)(NB * (iter + 1)));

            if (gvalid) {
                const float* gha = g_gh + ((iter & 1) * 2 + 0) * BATCH * NCOLS + gb * NCOLS;
                const float* ghb = g_gh + ((iter & 1) * 2 + 1) * BATCH * NCOLS + gb * NCOLS;
                if (glayer == 0) {
                    if (iter < T_SEQ) {
                        float hr[4], hz[4], hn[4];
#pragma unroll
                        for (int j = 0; j < 4; j++) { hr[j] = B1r[j]; hz[j] = B1z[j]; hn[j] = B1n[j]; }
                        if (iter > 0) {
                            ADD4_(hr, gha + gh4);            ADD4_(hr, ghb + gh4);
                            ADD4_(hz, gha + HDIM + gh4);     ADD4_(hz, ghb + HDIM + gh4);
                            ADD4_(hn, gha + 2 * HDIM + gh4); ADD4_(hn, ghb + 2 * HDIM + gh4);
                        }
#pragma unroll
                        for (int j = 0; j < 4; j++) {
                            float r = fsig_(pxr[j] + hr[j]);
                            float z = fsig_(pxz[j] + hz[j]);
                            float n = ftanh_(pxn[j] + r * hn[j]);
                            hp[j] = (1.0f - z) * n + z * hp[j];
                        }
                        const int off = (iter * BATCH + gb) * HDIM + gh4;
                        *reinterpret_cast<uint2*>(&g_h1f[off]) =
                            pack4h_(make_float4(hp[0], hp[1], hp[2], hp[3]));
                    }
                } else {
                    if (iter >= 1) {
                        const int t = iter - 1;
                        float xr[4], xz[4], xn[4], hr[4], hz[4], hn[4];
#pragma unroll
                        for (int j = 0; j < 4; j++) {
                            xr[j] = B2r[j]; xz[j] = B2z[j]; xn[j] = B2n[j];
                            hr[j] = B1r[j]; hz[j] = B1z[j]; hn[j] = B1n[j];
                        }
                        ADD4_(xr, gha + G3 + gh4);            ADD4_(xr, ghb + G3 + gh4);
                        ADD4_(xz, gha + G3 + HDIM + gh4);     ADD4_(xz, ghb + G3 + HDIM + gh4);
                        ADD4_(xn, gha + G3 + 2 * HDIM + gh4); ADD4_(xn, ghb + G3 + 2 * HDIM + gh4);
                        if (t > 0) {
                            ADD4_(hr, gha + 2 * G3 + gh4);            ADD4_(hr, ghb + 2 * G3 + gh4);
                            ADD4_(hz, gha + 2 * G3 + HDIM + gh4);     ADD4_(hz, ghb + 2 * G3 + HDIM + gh4);
                            ADD4_(hn, gha + 2 * G3 + 2 * HDIM + gh4); ADD4_(hn, ghb + 2 * G3 + 2 * HDIM + gh4);
                        }
#pragma unroll
                        for (int j = 0; j < 4; j++) {
                            float r = fsig_(xr[j] + hr[j]);
                            float z = fsig_(xz[j] + hz[j]);
                            float n = ftanh_(xn[j] + r * hn[j]);
                            hp[j] = (1.0f - z) * n + z * hp[j];
                        }
                        const int off = (t * BATCH + gb) * HDIM + gh4;
                        *reinterpret_cast<float4*>(&g_h2h[off]) =
                            make_float4(hp[0], hp[1], hp[2], hp[3]);
                        *reinterpret_cast<uint2*>(&g_h2f[off]) =
                            pack4h_(make_float4(hp[0], hp[1], hp[2], hp[3]));
                    }
                }
            }
            arrive_(&g_hdone);   // gate iteration complete
        }
    }
}

// =====================================================================
// pooled[t][h] = mean_b h2[t][b][h];  out[t][l] = pooled . fc_W[l] + fc_b[l]
// =====================================================================
__global__ __launch_bounds__(512) void final_kernel(const float* __restrict__ fc_W,
                                                    const float* __restrict__ fc_b,
                                                    float* __restrict__ out) {
    __shared__ float pooled[HDIM];
    const int t = blockIdx.x;
    const int h = threadIdx.x;

    float s = 0.0f;
    const float* base = &g_h2h[t * BATCH * HDIM + h];
#pragma unroll 8
    for (int b = 0; b < BATCH; ++b) s += base[b * HDIM];
    pooled[h] = s * (1.0f / (float)BATCH);
    __syncthreads();

    const int w = h >> 5, lane = h & 31;
    if (w < 5) {
        float acc = 0.0f;
        for (int k = lane; k < HDIM; k += 32) acc += pooled[k] * fc_W[w * HDIM + k];
#pragma unroll
        for (int o = 16; o > 0; o >>= 1) acc += __shfl_xor_sync(0xFFFFFFFFu, acc, o);
        if (lane == 0) out[t * 5 + w] = acc + fc_b[w];
    }
}

// =====================================================================
// reset flags before each replay (graph-capturable, deterministic)
// =====================================================================
__global__ void reset_flags_kernel() {
    g_ghdone = 0u;
    g_hdone = 0u;
}

extern "C" void kernel_launch(void* const* d_in, const int* in_sizes, int n_in,
                              void* d_out, int out_size) {
    const int*   texts = (const int*)  d_in[0];
    const float* emb   = (const float*)d_in[1];
    const float* Wih0  = (const float*)d_in[2];
    const float* Whh0  = (const float*)d_in[3];
    const float* bih0  = (const float*)d_in[4];
    const float* bhh0  = (const float*)d_in[5];
    const float* Wih1  = (const float*)d_in[6];
    const float* Whh1  = (const float*)d_in[7];
    const float* bih1  = (const float*)d_in[8];
    const float* bhh1  = (const float*)d_in[9];
    const float* fc_W  = (const float*)d_in[10];
    const float* fc_b  = (const float*)d_in[11];
    float* out = (float*)d_out;

    cudaFuncSetAttribute(xp0_mma_kernel,
                         cudaFuncAttributeMaxDynamicSharedMemorySize, SMEM_XP0);
    cudaFuncSetAttribute(recurrence_kernel,
                         cudaFuncAttributeMaxDynamicSharedMemorySize, SMEM_REC);

    reset_flags_kernel<<<1, 1>>>();
    prep_kernel<<<(PREP_E + PREP_W + 255) / 256, 256>>>(emb, Wih0);
    xp0_mma_kernel<<<dim3(24, 512), 256, SMEM_XP0>>>(texts, bih0);
    recurrence_kernel<<<NB, 256, SMEM_REC>>>(Whh0, Wih1, Whh1, bhh0, bih1, bhh1);
    final_kernel<<<T_SEQ, 512>>>(fc_W, fc_b, out);
}